// round 1
// baseline (speedup 1.0000x reference)
#include <cuda_runtime.h>
#include <math.h>

// Problem constants (fixed by the reference)
#define NTOK   4096     // B*T
#define CDIM   1024
#define EDIM   8
#define FDIM   1024
#define FSDIM  2048
#define NPAIR  8192     // NTOK * TOP_K

// ---------------- scratch (static __device__, allocation-free) ----------------
__device__ float g_mid[NPAIR * FDIM];   // 32MB: shared-expert hidden (4096x2048) then MoE hidden (8192x1024)
__device__ int   g_counts[EDIM];
__device__ int   g_fill[EDIM];
__device__ int   g_off[EDIM];
__device__ int   g_tok_e[NPAIR];        // per token: 2 expert ids
__device__ float g_tok_w[NPAIR];        // per token: 2 renormalized weights
__device__ int   g_bin_tok[NPAIR];      // bin row -> token
__device__ float g_bin_w[NPAIR];        // bin row -> combine weight

// ---------------- small kernels ----------------
__global__ void init_kernel() {
    int i = threadIdx.x;
    if (i < EDIM) { g_counts[i] = 0; g_fill[i] = 0; }
}

// warp per token: logits = x . w_router^T, softmax, top-2 (lowest index on tie), renorm
__global__ void router_kernel(const float* __restrict__ x, const float* __restrict__ wr) {
    int gw   = (blockIdx.x * blockDim.x + threadIdx.x) >> 5;
    int lane = threadIdx.x & 31;
    if (gw >= NTOK) return;
    const float* xr = x + (size_t)gw * CDIM;
    float acc[EDIM] = {0.f, 0.f, 0.f, 0.f, 0.f, 0.f, 0.f, 0.f};
    for (int c = lane; c < CDIM; c += 32) {
        float xv = xr[c];
        #pragma unroll
        for (int e = 0; e < EDIM; e++) acc[e] = fmaf(xv, wr[e * CDIM + c], acc[e]);
    }
    #pragma unroll
    for (int e = 0; e < EDIM; e++) {
        #pragma unroll
        for (int o = 16; o; o >>= 1) acc[e] += __shfl_xor_sync(0xffffffffu, acc[e], o);
    }
    if (lane == 0) {
        float m = acc[0];
        #pragma unroll
        for (int e = 1; e < EDIM; e++) m = fmaxf(m, acc[e]);
        float p[EDIM];
        #pragma unroll
        for (int e = 0; e < EDIM; e++) p[e] = expf(acc[e] - m);
        int i0 = 0; float p0 = p[0];
        #pragma unroll
        for (int e = 1; e < EDIM; e++) if (p[e] > p0) { p0 = p[e]; i0 = e; }
        int i1 = (i0 == 0) ? 1 : 0; float p1 = p[i1];
        #pragma unroll
        for (int e = 0; e < EDIM; e++) if (e != i1 && e != i0 && p[e] > p1) { p1 = p[e]; i1 = e; }
        // fix scan: ensure lowest-index tie-break for second max (scan in order, skip i0)
        i1 = -1; p1 = -1.f;
        #pragma unroll
        for (int e = 0; e < EDIM; e++) if (e != i0 && p[e] > p1) { p1 = p[e]; i1 = e; }
        float s = p0 + p1;
        g_tok_e[2 * gw + 0] = i0;  g_tok_w[2 * gw + 0] = p0 / s;
        g_tok_e[2 * gw + 1] = i1;  g_tok_w[2 * gw + 1] = p1 / s;
        atomicAdd(&g_counts[i0], 1);
        atomicAdd(&g_counts[i1], 1);
    }
}

__global__ void offsets_kernel() {
    if (threadIdx.x == 0) {
        int s = 0;
        for (int e = 0; e < EDIM; e++) { g_off[e] = s; s += g_counts[e]; }
    }
}

__global__ void assign_kernel() {
    int t = blockIdx.x * blockDim.x + threadIdx.x;
    if (t >= NTOK) return;
    #pragma unroll
    for (int k = 0; k < 2; k++) {
        int e = g_tok_e[2 * t + k];
        int slot = atomicAdd(&g_fill[e], 1);
        int r = g_off[e] + slot;
        g_bin_tok[r] = t;
        g_bin_w[r]   = g_tok_w[2 * t + k];
    }
}

// ---------------- templated NT GEMM: Out[m,n] = sum_k A[m,k] * B[n,k] ----------------
// GATHER:  A row index = rowmap[rowbase + m]   (gather tokens into expert bins)
// SQRELU:  epilogue v = relu(v)^2
// SCATTER: epilogue atomicAdd(Out[rowmap[rowbase+m]*N + n], roww[rowbase+m] * v)
template<bool GATHER, bool SQRELU, bool SCATTER>
__global__ __launch_bounds__(256) void gemm_nt(
    const float* __restrict__ A, const float* __restrict__ Bbase, float* __restrict__ Out,
    int M, int N, int K,
    const int* __restrict__ rowmap, const float* __restrict__ roww,
    const int* __restrict__ counts, const int* __restrict__ offs, size_t bStride)
{
    constexpr int BM = 128, BN = 128, BK = 8;
    const int e    = blockIdx.z;
    const int Mloc = counts ? counts[e] : M;
    const int m0   = blockIdx.y * BM;
    if (m0 >= Mloc) return;
    const int rowbase = offs ? offs[e] : 0;
    const int n0   = blockIdx.x * BN;
    const float* B = Bbase + (size_t)e * bStride;

    __shared__ float As[BK][BM];
    __shared__ float Bs[BK][BN];

    const int tid  = threadIdx.x;
    const int tx   = tid & 15, ty = tid >> 4;
    const int lrow = tid >> 1, kv = tid & 1;

    const int  am     = m0 + lrow;
    const bool avalid = am < Mloc;
    int arow;
    if (GATHER) arow = avalid ? rowmap[rowbase + am] : 0;
    else        arow = rowbase + (avalid ? am : 0);

    const float* Arow = A + (size_t)arow * K;
    const float* Brow = B + (size_t)(n0 + lrow) * K;

    float acc[8][8];
    #pragma unroll
    for (int i = 0; i < 8; i++)
        #pragma unroll
        for (int j = 0; j < 8; j++) acc[i][j] = 0.f;

    for (int k0 = 0; k0 < K; k0 += BK) {
        float4 a4 = avalid ? *(const float4*)(Arow + k0 + kv * 4) : make_float4(0.f, 0.f, 0.f, 0.f);
        float4 b4 = *(const float4*)(Brow + k0 + kv * 4);
        As[kv * 4 + 0][lrow] = a4.x; As[kv * 4 + 1][lrow] = a4.y;
        As[kv * 4 + 2][lrow] = a4.z; As[kv * 4 + 3][lrow] = a4.w;
        Bs[kv * 4 + 0][lrow] = b4.x; Bs[kv * 4 + 1][lrow] = b4.y;
        Bs[kv * 4 + 2][lrow] = b4.z; Bs[kv * 4 + 3][lrow] = b4.w;
        __syncthreads();
        #pragma unroll
        for (int k = 0; k < BK; k++) {
            float4 a0 = *(const float4*)&As[k][ty * 8];
            float4 a1 = *(const float4*)&As[k][ty * 8 + 4];
            float4 b0 = *(const float4*)&Bs[k][tx * 8];
            float4 b1 = *(const float4*)&Bs[k][tx * 8 + 4];
            float av[8] = {a0.x, a0.y, a0.z, a0.w, a1.x, a1.y, a1.z, a1.w};
            float bv[8] = {b0.x, b0.y, b0.z, b0.w, b1.x, b1.y, b1.z, b1.w};
            #pragma unroll
            for (int i = 0; i < 8; i++)
                #pragma unroll
                for (int j = 0; j < 8; j++)
                    acc[i][j] = fmaf(av[i], bv[j], acc[i][j]);
        }
        __syncthreads();
    }

    // epilogue
    #pragma unroll
    for (int i = 0; i < 8; i++) {
        int mr = m0 + ty * 8 + i;
        if (mr >= Mloc) break;
        int   tok = 0; float w = 0.f;
        if (SCATTER) { tok = rowmap[rowbase + mr]; w = roww[rowbase + mr]; }
        #pragma unroll
        for (int j = 0; j < 8; j++) {
            float v = acc[i][j];
            if (SQRELU) v = (v > 0.f) ? v * v : 0.f;
            int nc = n0 + tx * 8 + j;
            if (SCATTER) atomicAdd(&Out[(size_t)tok * N + nc], w * v);
            else         Out[(size_t)(rowbase + mr) * N + nc] = v;
        }
    }
}

// ---------------- launch ----------------
extern "C" void kernel_launch(void* const* d_in, const int* in_sizes, int n_in,
                              void* d_out, int out_size) {
    const float* x   = (const float*)d_in[0];   // (4096, 1024)
    const float* wr  = (const float*)d_in[1];   // (8, 1024)
    const float* w1  = (const float*)d_in[2];   // (8, 1024, 1024)  (E,F,C)
    const float* w2  = (const float*)d_in[3];   // (8, 1024, 1024)  (E,C,F)
    const float* ws1 = (const float*)d_in[4];   // (2048, 1024)
    const float* ws2 = (const float*)d_in[5];   // (1024, 2048)
    float* out = (float*)d_out;                 // (4096, 1024)

    float* mid;     cudaGetSymbolAddress((void**)&mid,     g_mid);
    int*   bin_tok; cudaGetSymbolAddress((void**)&bin_tok, g_bin_tok);
    float* bin_w;   cudaGetSymbolAddress((void**)&bin_w,   g_bin_w);
    int*   counts;  cudaGetSymbolAddress((void**)&counts,  g_counts);
    int*   offs;    cudaGetSymbolAddress((void**)&offs,    g_off);

    // routing + dispatch
    init_kernel<<<1, 32>>>();
    router_kernel<<<(NTOK * 32) / 256, 256>>>(x, wr);
    offsets_kernel<<<1, 32>>>();
    assign_kernel<<<(NTOK + 255) / 256, 256>>>();

    // shared expert: mid = sqrelu(x @ ws1^T); out = mid @ ws2^T  (plain store, inits d_out)
    gemm_nt<false, true,  false><<<dim3(FSDIM / 128, NTOK / 128, 1), 256>>>(
        x, ws1, mid, NTOK, FSDIM, CDIM, nullptr, nullptr, nullptr, nullptr, 0);
    gemm_nt<false, false, false><<<dim3(CDIM / 128, NTOK / 128, 1), 256>>>(
        mid, ws2, out, NTOK, CDIM, FSDIM, nullptr, nullptr, nullptr, nullptr, 0);

    // MoE: per-expert binned GEMMs (gather A rows; scatter-add weighted output)
    gemm_nt<true,  true,  false><<<dim3(FDIM / 128, NPAIR / 128, EDIM), 256>>>(
        x, w1, mid, NPAIR, FDIM, CDIM, bin_tok, nullptr, counts, offs, (size_t)FDIM * CDIM);
    gemm_nt<false, false, true ><<<dim3(CDIM / 128, NPAIR / 128, EDIM), 256>>>(
        mid, w2, out, NPAIR, CDIM, FDIM, bin_tok, bin_w, counts, offs, (size_t)CDIM * FDIM);
}

// round 3
// speedup vs baseline: 1.6256x; 1.6256x over previous
#include <cuda_runtime.h>
#include <cuda_bf16.h>
#include <cstdint>
#include <math.h>

// Problem constants
#define NTOK   4096
#define CDIM   1024
#define EDIM   8
#define FDIM   1024
#define FSDIM  2048
#define NPAIR  8192

// ---------------- scratch ----------------
__device__ float g_mid[NPAIR * FDIM];   // 32MB intermediate (time-shared)
__device__ int   g_counts[EDIM];
__device__ int   g_fill[EDIM];
__device__ int   g_off[EDIM];
__device__ int   g_tok_e[NPAIR];
__device__ float g_tok_w[NPAIR];
__device__ int   g_bin_tok[NPAIR];
__device__ float g_bin_w[NPAIR];

// ---------------- routing kernels ----------------
__global__ void init_kernel() {
    int i = threadIdx.x;
    if (i < EDIM) { g_counts[i] = 0; g_fill[i] = 0; }
}

__global__ void router_kernel(const float* __restrict__ x, const float* __restrict__ wr) {
    int gw = (blockIdx.x * blockDim.x + threadIdx.x) >> 5;
    int lane = threadIdx.x & 31;
    if (gw >= NTOK) return;
    const float* xr = x + (size_t)gw * CDIM;
    float acc[EDIM] = {0.f, 0.f, 0.f, 0.f, 0.f, 0.f, 0.f, 0.f};
    for (int c = lane; c < CDIM; c += 32) {
        float xv = xr[c];
        #pragma unroll
        for (int e = 0; e < EDIM; e++) acc[e] = fmaf(xv, wr[e * CDIM + c], acc[e]);
    }
    #pragma unroll
    for (int e = 0; e < EDIM; e++) {
        #pragma unroll
        for (int o = 16; o; o >>= 1) acc[e] += __shfl_xor_sync(0xffffffffu, acc[e], o);
    }
    if (lane == 0) {
        float m = acc[0];
        #pragma unroll
        for (int e = 1; e < EDIM; e++) m = fmaxf(m, acc[e]);
        float p[EDIM];
        #pragma unroll
        for (int e = 0; e < EDIM; e++) p[e] = expf(acc[e] - m);
        int i0 = 0; float p0 = p[0];
        #pragma unroll
        for (int e = 1; e < EDIM; e++) if (p[e] > p0) { p0 = p[e]; i0 = e; }
        int i1 = -1; float p1 = -1.f;
        #pragma unroll
        for (int e = 0; e < EDIM; e++) if (e != i0 && p[e] > p1) { p1 = p[e]; i1 = e; }
        float s = p0 + p1;
        g_tok_e[2 * gw + 0] = i0;  g_tok_w[2 * gw + 0] = p0 / s;
        g_tok_e[2 * gw + 1] = i1;  g_tok_w[2 * gw + 1] = p1 / s;
        atomicAdd(&g_counts[i0], 1);
        atomicAdd(&g_counts[i1], 1);
    }
}

__global__ void offsets_kernel() {
    if (threadIdx.x == 0) {
        int s = 0;
        for (int e = 0; e < EDIM; e++) { g_off[e] = s; s += g_counts[e]; }
    }
}

__global__ void assign_kernel() {
    int t = blockIdx.x * blockDim.x + threadIdx.x;
    if (t >= NTOK) return;
    #pragma unroll
    for (int k = 0; k < 2; k++) {
        int e = g_tok_e[2 * t + k];
        int slot = atomicAdd(&g_fill[e], 1);
        int r = g_off[e] + slot;
        g_bin_tok[r] = t;
        g_bin_w[r]   = g_tok_w[2 * t + k];
    }
}

// ---------------- mma.sync bf16x3 GEMM (sm_80+ path; no arch-feature PTX) ----------------
// Out[m,n] = sum_k A[m,k] * B[n,k], fp32 in/out.
// EPI: 0 = sqrelu -> Out row (rowbase+m); 1 = plain -> Out row m; 2 = atomicAdd(Out[rowmap*N], w*v)
#define BM 128
#define BN 128
#define BKF 32                     // fp32 k per K-tile
#define STAGE_WORDS 8192           // Ah(2048) Al(2048) Bh(2048) Bl(2048) uint32 words
#define SMEM_BYTES (2 * STAGE_WORDS * 4)   // 64 KB double-buffered
#define A_LO 2048
#define B_HI 4096
#define B_LO 6144

__device__ __forceinline__ void mma_bf16(float* c, const uint32_t* a, const uint32_t* b) {
    asm volatile(
        "mma.sync.aligned.m16n8k16.row.col.f32.bf16.bf16.f32 "
        "{%0,%1,%2,%3}, {%4,%5,%6,%7}, {%8,%9}, {%0,%1,%2,%3};"
        : "+f"(c[0]), "+f"(c[1]), "+f"(c[2]), "+f"(c[3])
        : "r"(a[0]), "r"(a[1]), "r"(a[2]), "r"(a[3]), "r"(b[0]), "r"(b[1]));
}

__device__ __forceinline__ void cvt8(float4 f0, float4 f1, uint4& hi, uint4& lo) {
    float v[8] = {f0.x, f0.y, f0.z, f0.w, f1.x, f1.y, f1.z, f1.w};
    unsigned short h[8], l[8];
    #pragma unroll
    for (int i = 0; i < 8; i++) {
        __nv_bfloat16 bh = __float2bfloat16_rn(v[i]);
        h[i] = __bfloat16_as_ushort(bh);
        l[i] = __bfloat16_as_ushort(__float2bfloat16_rn(v[i] - __bfloat162float(bh)));
    }
    hi.x = (uint32_t)h[0] | ((uint32_t)h[1] << 16);
    hi.y = (uint32_t)h[2] | ((uint32_t)h[3] << 16);
    hi.z = (uint32_t)h[4] | ((uint32_t)h[5] << 16);
    hi.w = (uint32_t)h[6] | ((uint32_t)h[7] << 16);
    lo.x = (uint32_t)l[0] | ((uint32_t)l[1] << 16);
    lo.y = (uint32_t)l[2] | ((uint32_t)l[3] << 16);
    lo.z = (uint32_t)l[4] | ((uint32_t)l[5] << 16);
    lo.w = (uint32_t)l[6] | ((uint32_t)l[7] << 16);
}

__device__ __forceinline__ float sqrelu(float v) { return v > 0.f ? v * v : 0.f; }

template<bool GATHER, int EPI>
__global__ __launch_bounds__(256) void mma_gemm(
    const float* __restrict__ A, const float* __restrict__ Bbase, float* __restrict__ Out,
    int N, int K,
    const int* __restrict__ rowmap, const float* __restrict__ roww,
    const int* __restrict__ counts, const int* __restrict__ offs, size_t bStride)
{
    const int e    = blockIdx.z;
    const int Mtot = counts ? counts[e] : (int)(gridDim.y * BM);
    const int m0   = blockIdx.y * BM;
    if (m0 >= Mtot) return;
    const int rowbase = offs ? offs[e] : 0;
    const int n0   = blockIdx.x * BN;
    const float* B = Bbase + (size_t)e * bStride;

    extern __shared__ uint32_t smw[];

    const int tid  = threadIdx.x;
    const int wid  = tid >> 5, lane = tid & 31;
    const int wm   = wid >> 2, wn = wid & 3;

    // ---- loader setup: each thread owns 2 A-chunks and 2 B-chunks (row, k-octet) ----
    const float* aptr[2]; const float* bptr[2];
    uint32_t aoff[2], boff[2];
    #pragma unroll
    for (int j = 0; j < 2; j++) {
        int c = tid + j * 256;
        int row = c >> 2, o = c & 3;              // row 0..127, octet 0..3 (8 fp32 each)
        int am = m0 + row;
        size_t arow;
        if (GATHER) arow = (size_t)rowmap[rowbase + (am < Mtot ? am : 0)];
        else        arow = (size_t)(rowbase + (am < Mtot ? am : m0));
        aptr[j] = A + arow * K + o * 8;
        bptr[j] = B + (size_t)(n0 + row) * K + o * 8;
        int ks = o >> 1, ch = o & 1;
        // A fragment-direct: [kstep(2)][m16(8)][reg(4)][lane(32)]
        aoff[j] = (uint32_t)(((ks * 8 + (row >> 4)) * 4 + (((row >> 3) & 1) + 2 * ch)) * 32 + (row & 7) * 4);
        // B fragment-direct: [kstep(2)][n8(16)][reg(2)][lane(32)]
        boff[j] = (uint32_t)(((ks * 16 + (row >> 3)) * 2 + ch) * 32 + (row & 7) * 4);
    }

    uint4 pah[2], pal[2], pbh[2], pbl[2];

    float acc[4][4][4];
    #pragma unroll
    for (int i = 0; i < 4; i++)
        #pragma unroll
        for (int j = 0; j < 4; j++)
            #pragma unroll
            for (int r = 0; r < 4; r++) acc[i][j][r] = 0.f;

    const int nK = K / BKF;

    // prefetch k-tile 0
    #pragma unroll
    for (int j = 0; j < 2; j++) {
        const float4* pa = (const float4*)aptr[j];
        cvt8(__ldg(pa), __ldg(pa + 1), pah[j], pal[j]);
        const float4* pb = (const float4*)bptr[j];
        cvt8(__ldg(pb), __ldg(pb + 1), pbh[j], pbl[j]);
    }

    for (int kt = 0; kt < nK; kt++) {
        const uint32_t sb = (kt & 1) * STAGE_WORDS;
        // store prefetched tile
        #pragma unroll
        for (int j = 0; j < 2; j++) {
            *(uint4*)&smw[sb +        aoff[j]] = pah[j];
            *(uint4*)&smw[sb + A_LO + aoff[j]] = pal[j];
            *(uint4*)&smw[sb + B_HI + boff[j]] = pbh[j];
            *(uint4*)&smw[sb + B_LO + boff[j]] = pbl[j];
        }
        __syncthreads();

        // prefetch next tile (overlaps with MMA below)
        if (kt + 1 < nK) {
            #pragma unroll
            for (int j = 0; j < 2; j++) {
                const float4* pa = (const float4*)(aptr[j] + (size_t)(kt + 1) * BKF);
                cvt8(__ldg(pa), __ldg(pa + 1), pah[j], pal[j]);
                const float4* pb = (const float4*)(bptr[j] + (size_t)(kt + 1) * BKF);
                cvt8(__ldg(pb), __ldg(pb + 1), pbh[j], pbl[j]);
            }
        }

        // compute on current buffer
        #pragma unroll
        for (int s = 0; s < 2; s++) {
            uint32_t bh[4][2], bl[4][2];
            #pragma unroll
            for (int j = 0; j < 4; j++) {
                uint32_t off = (uint32_t)(((s * 16 + wn * 4 + j) * 2) * 32 + lane);
                bh[j][0] = smw[sb + B_HI + off];  bh[j][1] = smw[sb + B_HI + off + 32];
                bl[j][0] = smw[sb + B_LO + off];  bl[j][1] = smw[sb + B_LO + off + 32];
            }
            #pragma unroll
            for (int i = 0; i < 4; i++) {
                uint32_t ah[4], al[4];
                uint32_t off = (uint32_t)(((s * 8 + wm * 4 + i) * 4) * 32 + lane);
                #pragma unroll
                for (int r = 0; r < 4; r++) {
                    ah[r] = smw[sb +        off + r * 32];
                    al[r] = smw[sb + A_LO + off + r * 32];
                }
                #pragma unroll
                for (int j = 0; j < 4; j++) mma_bf16(acc[i][j], ah, bh[j]);
                #pragma unroll
                for (int j = 0; j < 4; j++) mma_bf16(acc[i][j], al, bh[j]);
                #pragma unroll
                for (int j = 0; j < 4; j++) mma_bf16(acc[i][j], ah, bl[j]);
            }
        }
    }

    // ---- epilogue ----
    #pragma unroll
    for (int i = 0; i < 4; i++) {
        const int rbase = m0 + wm * 64 + i * 16 + (lane >> 2);
        #pragma unroll
        for (int half = 0; half < 2; half++) {
            const int mrow = rbase + half * 8;
            if (mrow >= Mtot) continue;
            int tok = 0; float w = 0.f;
            if (EPI == 2) { tok = rowmap[rowbase + mrow]; w = roww[rowbase + mrow]; }
            #pragma unroll
            for (int j = 0; j < 4; j++) {
                const int col = n0 + wn * 32 + j * 8 + (lane & 3) * 2;
                float v0 = acc[i][j][half * 2 + 0];
                float v1 = acc[i][j][half * 2 + 1];
                if (EPI == 0) {
                    float2 o2; o2.x = sqrelu(v0); o2.y = sqrelu(v1);
                    *(float2*)&Out[(size_t)(rowbase + mrow) * N + col] = o2;
                } else if (EPI == 1) {
                    float2 o2; o2.x = v0; o2.y = v1;
                    *(float2*)&Out[(size_t)mrow * N + col] = o2;
                } else {
                    atomicAdd(&Out[(size_t)tok * N + col],     w * v0);
                    atomicAdd(&Out[(size_t)tok * N + col + 1], w * v1);
                }
            }
        }
    }
}

// ---------------- launch ----------------
extern "C" void kernel_launch(void* const* d_in, const int* in_sizes, int n_in,
                              void* d_out, int out_size) {
    const float* x   = (const float*)d_in[0];
    const float* wr  = (const float*)d_in[1];
    const float* w1  = (const float*)d_in[2];   // (E, F, C)
    const float* w2  = (const float*)d_in[3];   // (E, C, F)
    const float* ws1 = (const float*)d_in[4];   // (FS, C)
    const float* ws2 = (const float*)d_in[5];   // (C, FS)
    float* out = (float*)d_out;

    float* mid;     cudaGetSymbolAddress((void**)&mid,     g_mid);
    int*   bin_tok; cudaGetSymbolAddress((void**)&bin_tok, g_bin_tok);
    float* bin_w;   cudaGetSymbolAddress((void**)&bin_w,   g_bin_w);
    int*   counts;  cudaGetSymbolAddress((void**)&counts,  g_counts);
    int*   offs;    cudaGetSymbolAddress((void**)&offs,    g_off);

    cudaFuncSetAttribute(mma_gemm<false, 0>, cudaFuncAttributeMaxDynamicSharedMemorySize, SMEM_BYTES);
    cudaFuncSetAttribute(mma_gemm<false, 1>, cudaFuncAttributeMaxDynamicSharedMemorySize, SMEM_BYTES);
    cudaFuncSetAttribute(mma_gemm<true,  0>, cudaFuncAttributeMaxDynamicSharedMemorySize, SMEM_BYTES);
    cudaFuncSetAttribute(mma_gemm<false, 2>, cudaFuncAttributeMaxDynamicSharedMemorySize, SMEM_BYTES);

    // routing
    init_kernel<<<1, 32>>>();
    router_kernel<<<(NTOK * 32) / 256, 256>>>(x, wr);
    offsets_kernel<<<1, 32>>>();
    assign_kernel<<<(NTOK + 255) / 256, 256>>>();

    // shared expert: mid = sqrelu(x @ ws1^T); out = mid @ ws2^T
    mma_gemm<false, 0><<<dim3(FSDIM / BN, NTOK / BM, 1), 256, SMEM_BYTES>>>(
        x, ws1, mid, FSDIM, CDIM, nullptr, nullptr, nullptr, nullptr, 0);
    mma_gemm<false, 1><<<dim3(CDIM / BN, NTOK / BM, 1), 256, SMEM_BYTES>>>(
        mid, ws2, out, CDIM, FSDIM, nullptr, nullptr, nullptr, nullptr, 0);

    // MoE experts: gather -> FFN1 -> sqrelu -> FFN2 -> weighted scatter-add
    mma_gemm<true, 0><<<dim3(FDIM / BN, NPAIR / BM, EDIM), 256, SMEM_BYTES>>>(
        x, w1, mid, FDIM, CDIM, bin_tok, nullptr, counts, offs, (size_t)FDIM * CDIM);
    mma_gemm<false, 2><<<dim3(CDIM / BN, NPAIR / BM, EDIM), 256, SMEM_BYTES>>>(
        mid, w2, out, CDIM, FDIM, bin_tok, bin_w, counts, offs, (size_t)CDIM * FDIM);
}

// round 4
// speedup vs baseline: 1.9735x; 1.2140x over previous
#include <cuda_runtime.h>
#include <cuda_bf16.h>
#include <cstdint>
#include <math.h>

// Problem constants
#define NTOK   4096
#define CDIM   1024
#define EDIM   8
#define FDIM   1024
#define FSDIM  2048
#define NPAIR  8192

// ---------------- scratch: pre-split bf16 operands ----------------
__device__ __nv_bfloat16 g_xh[NTOK * CDIM],  g_xl[NTOK * CDIM];      // 4M
__device__ __nv_bfloat16 g_w1h[EDIM * FDIM * CDIM], g_w1l[EDIM * FDIM * CDIM];   // 8M
__device__ __nv_bfloat16 g_w2h[EDIM * CDIM * FDIM], g_w2l[EDIM * CDIM * FDIM];   // 8M
__device__ __nv_bfloat16 g_ws1h[FSDIM * CDIM], g_ws1l[FSDIM * CDIM]; // 2M
__device__ __nv_bfloat16 g_ws2h[CDIM * FSDIM], g_ws2l[CDIM * FSDIM]; // 2M
__device__ __nv_bfloat16 g_midh[NPAIR * FDIM], g_midl[NPAIR * FDIM]; // 8M (also holds 4096x2048)
__device__ int   g_counts[EDIM];
__device__ int   g_fill[EDIM];
__device__ int   g_off[EDIM];
__device__ int   g_tok_e[NPAIR];
__device__ float g_tok_w[NPAIR];
__device__ int   g_bin_tok[NPAIR];
__device__ float g_bin_w[NPAIR];

// ---------------- helpers ----------------
__device__ __forceinline__ uint32_t smem_u32(const void* p) {
    uint32_t a;
    asm("{ .reg .u64 t; cvta.to.shared.u64 t, %1; cvt.u32.u64 %0, t; }" : "=r"(a) : "l"(p));
    return a;
}
__device__ __forceinline__ void cp_async16(uint32_t dst, const void* src) {
    asm volatile("cp.async.ca.shared.global [%0], [%1], 16;" :: "r"(dst), "l"(src));
}
#define CP_COMMIT() asm volatile("cp.async.commit_group;" ::: "memory")
#define CP_WAIT2()  asm volatile("cp.async.wait_group 2;" ::: "memory")

__device__ __forceinline__ void mma_bf16(float* c, const uint32_t* a, const uint32_t* b) {
    asm volatile(
        "mma.sync.aligned.m16n8k16.row.col.f32.bf16.bf16.f32 "
        "{%0,%1,%2,%3}, {%4,%5,%6,%7}, {%8,%9}, {%0,%1,%2,%3};"
        : "+f"(c[0]), "+f"(c[1]), "+f"(c[2]), "+f"(c[3])
        : "r"(a[0]), "r"(a[1]), "r"(a[2]), "r"(a[3]), "r"(b[0]), "r"(b[1]));
}
__device__ __forceinline__ float sqrelu(float v) { return v > 0.f ? v * v : 0.f; }

// ---------------- split: fp32 -> (bf16 hi, bf16 lo) ----------------
__global__ void split_kernel(const float* __restrict__ src,
                             __nv_bfloat16* __restrict__ h, __nv_bfloat16* __restrict__ l, int n) {
    int i = (blockIdx.x * blockDim.x + threadIdx.x) * 4;
    if (i >= n) return;
    float4 v = *(const float4*)(src + i);
    float vv[4] = {v.x, v.y, v.z, v.w};
    ushort4 hh, ll;
    unsigned short* hp = &hh.x; unsigned short* lp = &ll.x;
    #pragma unroll
    for (int k = 0; k < 4; k++) {
        __nv_bfloat16 bh = __float2bfloat16_rn(vv[k]);
        hp[k] = __bfloat16_as_ushort(bh);
        lp[k] = __bfloat16_as_ushort(__float2bfloat16_rn(vv[k] - __bfloat162float(bh)));
    }
    *(ushort4*)(h + i) = hh;
    *(ushort4*)(l + i) = ll;
}

// ---------------- routing ----------------
__global__ void init_kernel() {
    int i = threadIdx.x;
    if (i < EDIM) { g_counts[i] = 0; g_fill[i] = 0; }
}

__global__ void router_kernel(const float* __restrict__ x, const float* __restrict__ wr) {
    int gw = (blockIdx.x * blockDim.x + threadIdx.x) >> 5;
    int lane = threadIdx.x & 31;
    if (gw >= NTOK) return;
    const float* xr = x + (size_t)gw * CDIM;
    float acc[EDIM] = {0.f, 0.f, 0.f, 0.f, 0.f, 0.f, 0.f, 0.f};
    for (int c = lane; c < CDIM; c += 32) {
        float xv = xr[c];
        #pragma unroll
        for (int e = 0; e < EDIM; e++) acc[e] = fmaf(xv, wr[e * CDIM + c], acc[e]);
    }
    #pragma unroll
    for (int e = 0; e < EDIM; e++) {
        #pragma unroll
        for (int o = 16; o; o >>= 1) acc[e] += __shfl_xor_sync(0xffffffffu, acc[e], o);
    }
    if (lane == 0) {
        float m = acc[0];
        #pragma unroll
        for (int e = 1; e < EDIM; e++) m = fmaxf(m, acc[e]);
        float p[EDIM];
        #pragma unroll
        for (int e = 0; e < EDIM; e++) p[e] = expf(acc[e] - m);
        int i0 = 0; float p0 = p[0];
        #pragma unroll
        for (int e = 1; e < EDIM; e++) if (p[e] > p0) { p0 = p[e]; i0 = e; }
        int i1 = -1; float p1 = -1.f;
        #pragma unroll
        for (int e = 0; e < EDIM; e++) if (e != i0 && p[e] > p1) { p1 = p[e]; i1 = e; }
        float s = p0 + p1;
        g_tok_e[2 * gw + 0] = i0;  g_tok_w[2 * gw + 0] = p0 / s;
        g_tok_e[2 * gw + 1] = i1;  g_tok_w[2 * gw + 1] = p1 / s;
        atomicAdd(&g_counts[i0], 1);
        atomicAdd(&g_counts[i1], 1);
    }
}

__global__ void offsets_kernel() {
    if (threadIdx.x == 0) {
        int s = 0;
        for (int e = 0; e < EDIM; e++) { g_off[e] = s; s += g_counts[e]; }
    }
}

__global__ void assign_kernel() {
    int t = blockIdx.x * blockDim.x + threadIdx.x;
    if (t >= NTOK) return;
    #pragma unroll
    for (int k = 0; k < 2; k++) {
        int e = g_tok_e[2 * t + k];
        int slot = atomicAdd(&g_fill[e], 1);
        int r = g_off[e] + slot;
        g_bin_tok[r] = t;
        g_bin_w[r]   = g_tok_w[2 * t + k];
    }
}

// ---------------- mma.sync bf16x3 GEMM, pre-split operands, cp.async 3-stage ----------------
// Out[m,n] = sum_k A[m,k]*B[n,k].  A = Ah+Al, B = Bh+Bl (bf16 pairs, row-major [.,K]).
// EPI: 0 = sqrelu -> (OutH,OutL) bf16 pair at row (rowbase+m)
//      1 = plain fp32 -> OutF row m
//      2 = atomicAdd(OutF[rowmap*N + n], w*v)
#define BM 128
#define BN 128
#define BKF 32
#define STAGE_WORDS 8192           // Ah(2048w) Al(2048w) Bh(2048w) Bl(2048w)
#define NSTAGE 3
#define SMEM_BYTES (NSTAGE * STAGE_WORDS * 4)   // 96 KB
#define A_LO 2048
#define B_HI 4096
#define B_LO 6144

template<bool GATHER, int EPI>
__global__ __launch_bounds__(256, 2) void mma_gemm(
    const __nv_bfloat16* __restrict__ Ah, const __nv_bfloat16* __restrict__ Al,
    const __nv_bfloat16* __restrict__ Bhb, const __nv_bfloat16* __restrict__ Blb,
    float* __restrict__ OutF, __nv_bfloat16* __restrict__ OutH, __nv_bfloat16* __restrict__ OutL,
    int N, int K,
    const int* __restrict__ rowmap, const float* __restrict__ roww,
    const int* __restrict__ counts, const int* __restrict__ offs, size_t bStride)
{
    const int e    = blockIdx.z;
    const int Mtot = counts ? counts[e] : (int)(gridDim.y * BM);
    const int m0   = blockIdx.y * BM;
    if (m0 >= Mtot) return;
    const int rowbase = offs ? offs[e] : 0;
    const int n0   = blockIdx.x * BN;
    const __nv_bfloat16* Bh = Bhb + (size_t)e * bStride;
    const __nv_bfloat16* Bl = Blb + (size_t)e * bStride;

    extern __shared__ uint32_t smw[];
    const uint32_t sm0 = smem_u32(smw);

    const int tid  = threadIdx.x;
    const int wid  = tid >> 5, lane = tid & 31;
    const int wm   = wid >> 2, wn = wid & 3;

    // loader: thread owns 2 chunks (row, k-octet) of each operand
    const __nv_bfloat16 *pah[2], *pal[2], *pbh[2], *pbl[2];
    uint32_t aoff[2], boff[2];
    #pragma unroll
    for (int j = 0; j < 2; j++) {
        int c = tid + j * 256;
        int row = c >> 2, o = c & 3;
        int am = m0 + row;
        size_t arow;
        if (GATHER) arow = (size_t)rowmap[rowbase + (am < Mtot ? am : 0)];
        else        arow = (size_t)(rowbase + (am < Mtot ? am : m0));
        pah[j] = Ah + arow * K + o * 8;
        pal[j] = Al + arow * K + o * 8;
        pbh[j] = Bh + (size_t)(n0 + row) * K + o * 8;
        pbl[j] = Bl + (size_t)(n0 + row) * K + o * 8;
        int ks = o >> 1, ch = o & 1;
        aoff[j] = (uint32_t)(((ks * 8 + (row >> 4)) * 4 + (((row >> 3) & 1) + 2 * ch)) * 32 + (row & 7) * 4) * 4u;
        boff[j] = (uint32_t)(((ks * 16 + (row >> 3)) * 2 + ch) * 32 + (row & 7) * 4) * 4u;
    }

    const int nK = K / BKF;

    float acc[4][4][4];
    #pragma unroll
    for (int i = 0; i < 4; i++)
        #pragma unroll
        for (int j = 0; j < 4; j++)
            #pragma unroll
            for (int r = 0; r < 4; r++) acc[i][j][r] = 0.f;

    // issue stage kt into buffer kt%NSTAGE
    auto issue = [&](int kt) {
        if (kt < nK) {
            const uint32_t sb = sm0 + (kt % NSTAGE) * (STAGE_WORDS * 4);
            const int kadv = kt * BKF;
            #pragma unroll
            for (int j = 0; j < 2; j++) {
                cp_async16(sb +             aoff[j], pah[j] + kadv);
                cp_async16(sb + A_LO * 4  + aoff[j], pal[j] + kadv);
                cp_async16(sb + B_HI * 4  + boff[j], pbh[j] + kadv);
                cp_async16(sb + B_LO * 4  + boff[j], pbl[j] + kadv);
            }
        }
        CP_COMMIT();
    };

    issue(0); issue(1); issue(2);

    for (int kt = 0; kt < nK; kt++) {
        CP_WAIT2();
        __syncthreads();
        const uint32_t sb = (kt % NSTAGE) * STAGE_WORDS;

        #pragma unroll
        for (int s = 0; s < 2; s++) {
            uint32_t bh[4][2], bl[4][2];
            #pragma unroll
            for (int j = 0; j < 4; j++) {
                uint32_t off = (uint32_t)(((s * 16 + wn * 4 + j) * 2) * 32 + lane);
                bh[j][0] = smw[sb + B_HI + off];  bh[j][1] = smw[sb + B_HI + off + 32];
                bl[j][0] = smw[sb + B_LO + off];  bl[j][1] = smw[sb + B_LO + off + 32];
            }
            #pragma unroll
            for (int i = 0; i < 4; i++) {
                uint32_t ah[4], al[4];
                uint32_t off = (uint32_t)(((s * 8 + wm * 4 + i) * 4) * 32 + lane);
                #pragma unroll
                for (int r = 0; r < 4; r++) {
                    ah[r] = smw[sb +        off + r * 32];
                    al[r] = smw[sb + A_LO + off + r * 32];
                }
                #pragma unroll
                for (int j = 0; j < 4; j++) mma_bf16(acc[i][j], ah, bh[j]);
                #pragma unroll
                for (int j = 0; j < 4; j++) mma_bf16(acc[i][j], al, bh[j]);
                #pragma unroll
                for (int j = 0; j < 4; j++) mma_bf16(acc[i][j], ah, bl[j]);
            }
        }
        __syncthreads();
        issue(kt + NSTAGE);
    }

    // ---- epilogue ----
    #pragma unroll
    for (int i = 0; i < 4; i++) {
        const int rbase = m0 + wm * 64 + i * 16 + (lane >> 2);
        #pragma unroll
        for (int half = 0; half < 2; half++) {
            const int mrow = rbase + half * 8;
            if (mrow >= Mtot) continue;
            int tok = 0; float w = 0.f;
            if (EPI == 2) { tok = rowmap[rowbase + mrow]; w = roww[rowbase + mrow]; }
            #pragma unroll
            for (int j = 0; j < 4; j++) {
                const int col = n0 + wn * 32 + j * 8 + (lane & 3) * 2;
                float v0 = acc[i][j][half * 2 + 0];
                float v1 = acc[i][j][half * 2 + 1];
                if (EPI == 0) {
                    float s0 = sqrelu(v0), s1 = sqrelu(v1);
                    __nv_bfloat16 h0 = __float2bfloat16_rn(s0);
                    __nv_bfloat16 h1 = __float2bfloat16_rn(s1);
                    ushort2 hh, ll;
                    hh.x = __bfloat16_as_ushort(h0);
                    hh.y = __bfloat16_as_ushort(h1);
                    ll.x = __bfloat16_as_ushort(__float2bfloat16_rn(s0 - __bfloat162float(h0)));
                    ll.y = __bfloat16_as_ushort(__float2bfloat16_rn(s1 - __bfloat162float(h1)));
                    size_t idx = (size_t)(rowbase + mrow) * N + col;
                    *(ushort2*)(OutH + idx) = hh;
                    *(ushort2*)(OutL + idx) = ll;
                } else if (EPI == 1) {
                    float2 o2; o2.x = v0; o2.y = v1;
                    *(float2*)&OutF[(size_t)mrow * N + col] = o2;
                } else {
                    atomicAdd(&OutF[(size_t)tok * N + col],     w * v0);
                    atomicAdd(&OutF[(size_t)tok * N + col + 1], w * v1);
                }
            }
        }
    }
}

// ---------------- launch ----------------
extern "C" void kernel_launch(void* const* d_in, const int* in_sizes, int n_in,
                              void* d_out, int out_size) {
    const float* x   = (const float*)d_in[0];
    const float* wr  = (const float*)d_in[1];
    const float* w1  = (const float*)d_in[2];   // (E, F, C)
    const float* w2  = (const float*)d_in[3];   // (E, C, F)
    const float* ws1 = (const float*)d_in[4];   // (FS, C)
    const float* ws2 = (const float*)d_in[5];   // (C, FS)
    float* out = (float*)d_out;

    __nv_bfloat16 *xh, *xl, *w1h, *w1l, *w2h, *w2l, *ws1h, *ws1l, *ws2h, *ws2l, *midh, *midl;
    cudaGetSymbolAddress((void**)&xh,   g_xh);   cudaGetSymbolAddress((void**)&xl,   g_xl);
    cudaGetSymbolAddress((void**)&w1h,  g_w1h);  cudaGetSymbolAddress((void**)&w1l,  g_w1l);
    cudaGetSymbolAddress((void**)&w2h,  g_w2h);  cudaGetSymbolAddress((void**)&w2l,  g_w2l);
    cudaGetSymbolAddress((void**)&ws1h, g_ws1h); cudaGetSymbolAddress((void**)&ws1l, g_ws1l);
    cudaGetSymbolAddress((void**)&ws2h, g_ws2h); cudaGetSymbolAddress((void**)&ws2l, g_ws2l);
    cudaGetSymbolAddress((void**)&midh, g_midh); cudaGetSymbolAddress((void**)&midl, g_midl);
    int *bin_tok, *counts, *offs; float* bin_w;
    cudaGetSymbolAddress((void**)&bin_tok, g_bin_tok);
    cudaGetSymbolAddress((void**)&bin_w,   g_bin_w);
    cudaGetSymbolAddress((void**)&counts,  g_counts);
    cudaGetSymbolAddress((void**)&offs,    g_off);

    cudaFuncSetAttribute(mma_gemm<false, 0>, cudaFuncAttributeMaxDynamicSharedMemorySize, SMEM_BYTES);
    cudaFuncSetAttribute(mma_gemm<false, 1>, cudaFuncAttributeMaxDynamicSharedMemorySize, SMEM_BYTES);
    cudaFuncSetAttribute(mma_gemm<true,  0>, cudaFuncAttributeMaxDynamicSharedMemorySize, SMEM_BYTES);
    cudaFuncSetAttribute(mma_gemm<false, 2>, cudaFuncAttributeMaxDynamicSharedMemorySize, SMEM_BYTES);

    // pre-split fp32 -> bf16 hi/lo
    auto split = [&](const float* s, __nv_bfloat16* h, __nv_bfloat16* l, int n) {
        split_kernel<<<(n / 4 + 255) / 256, 256>>>(s, h, l, n);
    };
    split(x,   xh,   xl,   NTOK * CDIM);
    split(ws1, ws1h, ws1l, FSDIM * CDIM);
    split(ws2, ws2h, ws2l, CDIM * FSDIM);
    split(w1,  w1h,  w1l,  EDIM * FDIM * CDIM);
    split(w2,  w2h,  w2l,  EDIM * CDIM * FDIM);

    // routing
    init_kernel<<<1, 32>>>();
    router_kernel<<<(NTOK * 32) / 256, 256>>>(x, wr);
    offsets_kernel<<<1, 32>>>();
    assign_kernel<<<(NTOK + 255) / 256, 256>>>();

    // shared expert: mid = sqrelu(x @ ws1^T); out = mid @ ws2^T
    mma_gemm<false, 0><<<dim3(FSDIM / BN, NTOK / BM, 1), 256, SMEM_BYTES>>>(
        xh, xl, ws1h, ws1l, nullptr, midh, midl, FSDIM, CDIM, nullptr, nullptr, nullptr, nullptr, 0);
    mma_gemm<false, 1><<<dim3(CDIM / BN, NTOK / BM, 1), 256, SMEM_BYTES>>>(
        midh, midl, ws2h, ws2l, out, nullptr, nullptr, CDIM, FSDIM, nullptr, nullptr, nullptr, nullptr, 0);

    // MoE experts: gather -> FFN1 -> sqrelu -> FFN2 -> weighted scatter-add
    mma_gemm<true, 0><<<dim3(FDIM / BN, NPAIR / BM, EDIM), 256, SMEM_BYTES>>>(
        xh, xl, w1h, w1l, nullptr, midh, midl, FDIM, CDIM, bin_tok, nullptr, counts, offs, (size_t)FDIM * CDIM);
    mma_gemm<false, 2><<<dim3(CDIM / BN, NPAIR / BM, EDIM), 256, SMEM_BYTES>>>(
        midh, midl, w2h, w2l, out, nullptr, nullptr, CDIM, FDIM, bin_tok, bin_w, counts, offs, (size_t)CDIM * FDIM);
}

// round 5
// speedup vs baseline: 2.7826x; 1.4100x over previous
#include <cuda_runtime.h>
#include <cuda_fp16.h>
#include <cstdint>
#include <math.h>

// Problem constants
#define NTOK   4096
#define CDIM   1024
#define EDIM   8
#define FDIM   1024
#define FSDIM  2048
#define NPAIR  8192

// ---------------- scratch ----------------
__device__ __half g_xh[NTOK * CDIM];                                  // activations, single fp16
__device__ __half g_w1h[EDIM * FDIM * CDIM], g_w1l[EDIM * FDIM * CDIM];
__device__ __half g_w2h[EDIM * CDIM * FDIM], g_w2l[EDIM * CDIM * FDIM];
__device__ __half g_ws1h[FSDIM * CDIM], g_ws1l[FSDIM * CDIM];
__device__ __half g_ws2h[CDIM * FSDIM], g_ws2l[CDIM * FSDIM];
__device__ __half g_midh[NPAIR * FDIM];                               // intermediate, single fp16
__device__ int   g_counts[EDIM];
__device__ int   g_fill[EDIM];
__device__ int   g_off[EDIM];
__device__ int   g_tok_e[NPAIR];
__device__ float g_tok_w[NPAIR];
__device__ int   g_bin_tok[NPAIR];
__device__ float g_bin_w[NPAIR];

// ---------------- helpers ----------------
__device__ __forceinline__ uint32_t smem_u32(const void* p) {
    uint32_t a;
    asm("{ .reg .u64 t; cvta.to.shared.u64 t, %1; cvt.u32.u64 %0, t; }" : "=r"(a) : "l"(p));
    return a;
}
__device__ __forceinline__ void cp_async16(uint32_t dst, const void* src) {
    asm volatile("cp.async.ca.shared.global [%0], [%1], 16;" :: "r"(dst), "l"(src));
}
#define CP_COMMIT() asm volatile("cp.async.commit_group;" ::: "memory")
#define CP_WAIT3()  asm volatile("cp.async.wait_group 3;" ::: "memory")

__device__ __forceinline__ void mma_f16(float* c, const uint32_t* a, const uint32_t* b) {
    asm volatile(
        "mma.sync.aligned.m16n8k16.row.col.f32.f16.f16.f32 "
        "{%0,%1,%2,%3}, {%4,%5,%6,%7}, {%8,%9}, {%0,%1,%2,%3};"
        : "+f"(c[0]), "+f"(c[1]), "+f"(c[2]), "+f"(c[3])
        : "r"(a[0]), "r"(a[1]), "r"(a[2]), "r"(a[3]), "r"(b[0]), "r"(b[1]));
}
__device__ __forceinline__ float sqrelu(float v) { return v > 0.f ? v * v : 0.f; }

// ---------------- conversions ----------------
__global__ void cvt_half_kernel(const float* __restrict__ src, __half* __restrict__ h, int n) {
    int i = (blockIdx.x * blockDim.x + threadIdx.x) * 4;
    if (i >= n) return;
    float4 v = *(const float4*)(src + i);
    ushort4 hh;
    hh.x = __half_as_ushort(__float2half_rn(v.x));
    hh.y = __half_as_ushort(__float2half_rn(v.y));
    hh.z = __half_as_ushort(__float2half_rn(v.z));
    hh.w = __half_as_ushort(__float2half_rn(v.w));
    *(ushort4*)(h + i) = hh;
}

__global__ void split_half_kernel(const float* __restrict__ src,
                                  __half* __restrict__ h, __half* __restrict__ l, int n) {
    int i = (blockIdx.x * blockDim.x + threadIdx.x) * 4;
    if (i >= n) return;
    float4 v = *(const float4*)(src + i);
    float vv[4] = {v.x, v.y, v.z, v.w};
    ushort4 hh, ll;
    unsigned short* hp = &hh.x; unsigned short* lp = &ll.x;
    #pragma unroll
    for (int k = 0; k < 4; k++) {
        __half bh = __float2half_rn(vv[k]);
        hp[k] = __half_as_ushort(bh);
        lp[k] = __half_as_ushort(__float2half_rn(vv[k] - __half2float(bh)));
    }
    *(ushort4*)(h + i) = hh;
    *(ushort4*)(l + i) = ll;
}

// ---------------- routing ----------------
__global__ void init_kernel() {
    int i = threadIdx.x;
    if (i < EDIM) { g_counts[i] = 0; g_fill[i] = 0; }
}

__global__ void router_kernel(const float* __restrict__ x, const float* __restrict__ wr) {
    int gw = (blockIdx.x * blockDim.x + threadIdx.x) >> 5;
    int lane = threadIdx.x & 31;
    if (gw >= NTOK) return;
    const float* xr = x + (size_t)gw * CDIM;
    float acc[EDIM] = {0.f, 0.f, 0.f, 0.f, 0.f, 0.f, 0.f, 0.f};
    for (int c = lane; c < CDIM; c += 32) {
        float xv = xr[c];
        #pragma unroll
        for (int e = 0; e < EDIM; e++) acc[e] = fmaf(xv, wr[e * CDIM + c], acc[e]);
    }
    #pragma unroll
    for (int e = 0; e < EDIM; e++) {
        #pragma unroll
        for (int o = 16; o; o >>= 1) acc[e] += __shfl_xor_sync(0xffffffffu, acc[e], o);
    }
    if (lane == 0) {
        float m = acc[0];
        #pragma unroll
        for (int e = 1; e < EDIM; e++) m = fmaxf(m, acc[e]);
        float p[EDIM];
        #pragma unroll
        for (int e = 0; e < EDIM; e++) p[e] = expf(acc[e] - m);
        int i0 = 0; float p0 = p[0];
        #pragma unroll
        for (int e = 1; e < EDIM; e++) if (p[e] > p0) { p0 = p[e]; i0 = e; }
        int i1 = -1; float p1 = -1.f;
        #pragma unroll
        for (int e = 0; e < EDIM; e++) if (e != i0 && p[e] > p1) { p1 = p[e]; i1 = e; }
        float s = p0 + p1;
        g_tok_e[2 * gw + 0] = i0;  g_tok_w[2 * gw + 0] = p0 / s;
        g_tok_e[2 * gw + 1] = i1;  g_tok_w[2 * gw + 1] = p1 / s;
        atomicAdd(&g_counts[i0], 1);
        atomicAdd(&g_counts[i1], 1);
    }
}

__global__ void offsets_kernel() {
    if (threadIdx.x == 0) {
        int s = 0;
        for (int e = 0; e < EDIM; e++) { g_off[e] = s; s += g_counts[e]; }
    }
}

__global__ void assign_kernel() {
    int t = blockIdx.x * blockDim.x + threadIdx.x;
    if (t >= NTOK) return;
    #pragma unroll
    for (int k = 0; k < 2; k++) {
        int e = g_tok_e[2 * t + k];
        int slot = atomicAdd(&g_fill[e], 1);
        int r = g_off[e] + slot;
        g_bin_tok[r] = t;
        g_bin_w[r]   = g_tok_w[2 * t + k];
    }
}

// ---------------- mma.sync fp16x2 GEMM, cp.async 4-stage ----------------
// Out[m,n] = sum_k A[m,k]*B[n,k].  A = single fp16, B = Bh + Bl (fp16 pair), row-major [.,K].
// EPI: 0 = sqrelu -> fp16 OutH row (rowbase+m); 1 = fp32 OutF row m; 2 = atomicAdd(OutF[rowmap*N], w*v)
#define BM 128
#define BN 128
#define BKF 32
#define STAGE_WORDS 6144           // A(2048w) Bh(2048w) Bl(2048w)
#define NSTAGE 4
#define SMEM_BYTES (NSTAGE * STAGE_WORDS * 4)   // 96 KB
#define B_HI 2048
#define B_LO 4096

template<bool GATHER, int EPI>
__global__ __launch_bounds__(256, 2) void mma_gemm(
    const __half* __restrict__ A,
    const __half* __restrict__ Bhb, const __half* __restrict__ Blb,
    float* __restrict__ OutF, __half* __restrict__ OutH,
    int N, int K,
    const int* __restrict__ rowmap, const float* __restrict__ roww,
    const int* __restrict__ counts, const int* __restrict__ offs, size_t bStride)
{
    const int e    = blockIdx.z;
    const int Mtot = counts ? counts[e] : (int)(gridDim.y * BM);
    const int m0   = blockIdx.y * BM;
    if (m0 >= Mtot) return;
    const int rowbase = offs ? offs[e] : 0;
    const int n0   = blockIdx.x * BN;
    const __half* Bh = Bhb + (size_t)e * bStride;
    const __half* Bl = Blb + (size_t)e * bStride;

    extern __shared__ uint32_t smw[];
    const uint32_t sm0 = smem_u32(smw);

    const int tid  = threadIdx.x;
    const int wid  = tid >> 5, lane = tid & 31;
    const int wm   = wid >> 2, wn = wid & 3;

    // loader: thread owns 2 chunks (row, k-octet) of each operand
    const __half *pa[2], *pbh[2], *pbl[2];
    uint32_t aoff[2], boff[2];
    #pragma unroll
    for (int j = 0; j < 2; j++) {
        int c = tid + j * 256;
        int row = c >> 2, o = c & 3;
        int am = m0 + row;
        size_t arow;
        if (GATHER) arow = (size_t)rowmap[rowbase + (am < Mtot ? am : 0)];
        else        arow = (size_t)(rowbase + (am < Mtot ? am : m0));
        pa[j]  = A  + arow * K + o * 8;
        pbh[j] = Bh + (size_t)(n0 + row) * K + o * 8;
        pbl[j] = Bl + (size_t)(n0 + row) * K + o * 8;
        int ks = o >> 1, ch = o & 1;
        aoff[j] = (uint32_t)(((ks * 8 + (row >> 4)) * 4 + (((row >> 3) & 1) + 2 * ch)) * 32 + (row & 7) * 4) * 4u;
        boff[j] = (uint32_t)(((ks * 16 + (row >> 3)) * 2 + ch) * 32 + (row & 7) * 4) * 4u;
    }

    const int nK = K / BKF;

    float acc[4][4][4];
    #pragma unroll
    for (int i = 0; i < 4; i++)
        #pragma unroll
        for (int j = 0; j < 4; j++)
            #pragma unroll
            for (int r = 0; r < 4; r++) acc[i][j][r] = 0.f;

    auto issue = [&](int kt) {
        if (kt < nK) {
            const uint32_t sb = sm0 + (kt % NSTAGE) * (STAGE_WORDS * 4);
            const int kadv = kt * BKF;
            #pragma unroll
            for (int j = 0; j < 2; j++) {
                cp_async16(sb +            aoff[j], pa[j]  + kadv);
                cp_async16(sb + B_HI * 4 + boff[j], pbh[j] + kadv);
                cp_async16(sb + B_LO * 4 + boff[j], pbl[j] + kadv);
            }
        }
        CP_COMMIT();
    };

    issue(0); issue(1); issue(2); issue(3);

    for (int kt = 0; kt < nK; kt++) {
        CP_WAIT3();
        __syncthreads();
        const uint32_t sb = (kt % NSTAGE) * STAGE_WORDS;

        #pragma unroll
        for (int s = 0; s < 2; s++) {
            uint32_t bh[4][2], bl[4][2];
            #pragma unroll
            for (int j = 0; j < 4; j++) {
                uint32_t off = (uint32_t)(((s * 16 + wn * 4 + j) * 2) * 32 + lane);
                bh[j][0] = smw[sb + B_HI + off];  bh[j][1] = smw[sb + B_HI + off + 32];
                bl[j][0] = smw[sb + B_LO + off];  bl[j][1] = smw[sb + B_LO + off + 32];
            }
            #pragma unroll
            for (int i = 0; i < 4; i++) {
                uint32_t a[4];
                uint32_t off = (uint32_t)(((s * 8 + wm * 4 + i) * 4) * 32 + lane);
                #pragma unroll
                for (int r = 0; r < 4; r++) a[r] = smw[sb + off + r * 32];
                #pragma unroll
                for (int j = 0; j < 4; j++) mma_f16(acc[i][j], a, bh[j]);
                #pragma unroll
                for (int j = 0; j < 4; j++) mma_f16(acc[i][j], a, bl[j]);
            }
        }
        __syncthreads();
        issue(kt + NSTAGE);
    }

    // ---- epilogue ----
    #pragma unroll
    for (int i = 0; i < 4; i++) {
        const int rbase = m0 + wm * 64 + i * 16 + (lane >> 2);
        #pragma unroll
        for (int half = 0; half < 2; half++) {
            const int mrow = rbase + half * 8;
            if (mrow >= Mtot) continue;
            int tok = 0; float w = 0.f;
            if (EPI == 2) { tok = rowmap[rowbase + mrow]; w = roww[rowbase + mrow]; }
            #pragma unroll
            for (int j = 0; j < 4; j++) {
                const int col = n0 + wn * 32 + j * 8 + (lane & 3) * 2;
                float v0 = acc[i][j][half * 2 + 0];
                float v1 = acc[i][j][half * 2 + 1];
                if (EPI == 0) {
                    __half2 h2 = __floats2half2_rn(sqrelu(v0), sqrelu(v1));
                    *(__half2*)(OutH + (size_t)(rowbase + mrow) * N + col) = h2;
                } else if (EPI == 1) {
                    float2 o2; o2.x = v0; o2.y = v1;
                    *(float2*)&OutF[(size_t)mrow * N + col] = o2;
                } else {
                    atomicAdd(&OutF[(size_t)tok * N + col],     w * v0);
                    atomicAdd(&OutF[(size_t)tok * N + col + 1], w * v1);
                }
            }
        }
    }
}

// ---------------- launch ----------------
extern "C" void kernel_launch(void* const* d_in, const int* in_sizes, int n_in,
                              void* d_out, int out_size) {
    const float* x   = (const float*)d_in[0];
    const float* wr  = (const float*)d_in[1];
    const float* w1  = (const float*)d_in[2];   // (E, F, C)
    const float* w2  = (const float*)d_in[3];   // (E, C, F)
    const float* ws1 = (const float*)d_in[4];   // (FS, C)
    const float* ws2 = (const float*)d_in[5];   // (C, FS)
    float* out = (float*)d_out;

    __half *xh, *w1h, *w1l, *w2h, *w2l, *ws1h, *ws1l, *ws2h, *ws2l, *midh;
    cudaGetSymbolAddress((void**)&xh,   g_xh);
    cudaGetSymbolAddress((void**)&w1h,  g_w1h);  cudaGetSymbolAddress((void**)&w1l,  g_w1l);
    cudaGetSymbolAddress((void**)&w2h,  g_w2h);  cudaGetSymbolAddress((void**)&w2l,  g_w2l);
    cudaGetSymbolAddress((void**)&ws1h, g_ws1h); cudaGetSymbolAddress((void**)&ws1l, g_ws1l);
    cudaGetSymbolAddress((void**)&ws2h, g_ws2h); cudaGetSymbolAddress((void**)&ws2l, g_ws2l);
    cudaGetSymbolAddress((void**)&midh, g_midh);
    int *bin_tok, *counts, *offs; float* bin_w;
    cudaGetSymbolAddress((void**)&bin_tok, g_bin_tok);
    cudaGetSymbolAddress((void**)&bin_w,   g_bin_w);
    cudaGetSymbolAddress((void**)&counts,  g_counts);
    cudaGetSymbolAddress((void**)&offs,    g_off);

    cudaFuncSetAttribute(mma_gemm<false, 0>, cudaFuncAttributeMaxDynamicSharedMemorySize, SMEM_BYTES);
    cudaFuncSetAttribute(mma_gemm<false, 1>, cudaFuncAttributeMaxDynamicSharedMemorySize, SMEM_BYTES);
    cudaFuncSetAttribute(mma_gemm<true,  0>, cudaFuncAttributeMaxDynamicSharedMemorySize, SMEM_BYTES);
    cudaFuncSetAttribute(mma_gemm<false, 2>, cudaFuncAttributeMaxDynamicSharedMemorySize, SMEM_BYTES);

    // conversions
    cvt_half_kernel<<<(NTOK * CDIM / 4 + 255) / 256, 256>>>(x, xh, NTOK * CDIM);
    split_half_kernel<<<(FSDIM * CDIM / 4 + 255) / 256, 256>>>(ws1, ws1h, ws1l, FSDIM * CDIM);
    split_half_kernel<<<(CDIM * FSDIM / 4 + 255) / 256, 256>>>(ws2, ws2h, ws2l, CDIM * FSDIM);
    split_half_kernel<<<(EDIM * FDIM * CDIM / 4 + 255) / 256, 256>>>(w1, w1h, w1l, EDIM * FDIM * CDIM);
    split_half_kernel<<<(EDIM * CDIM * FDIM / 4 + 255) / 256, 256>>>(w2, w2h, w2l, EDIM * CDIM * FDIM);

    // routing
    init_kernel<<<1, 32>>>();
    router_kernel<<<(NTOK * 32) / 256, 256>>>(x, wr);
    offsets_kernel<<<1, 32>>>();
    assign_kernel<<<(NTOK + 255) / 256, 256>>>();

    // shared expert: mid = sqrelu(x @ ws1^T); out = mid @ ws2^T
    mma_gemm<false, 0><<<dim3(FSDIM / BN, NTOK / BM, 1), 256, SMEM_BYTES>>>(
        xh, ws1h, ws1l, nullptr, midh, FSDIM, CDIM, nullptr, nullptr, nullptr, nullptr, 0);
    mma_gemm<false, 1><<<dim3(CDIM / BN, NTOK / BM, 1), 256, SMEM_BYTES>>>(
        midh, ws2h, ws2l, out, nullptr, CDIM, FSDIM, nullptr, nullptr, nullptr, nullptr, 0);

    // MoE experts: gather -> FFN1 -> sqrelu -> FFN2 -> weighted scatter-add
    mma_gemm<true, 0><<<dim3(FDIM / BN, NPAIR / BM, EDIM), 256, SMEM_BYTES>>>(
        xh, w1h, w1l, nullptr, midh, FDIM, CDIM, bin_tok, nullptr, counts, offs, (size_t)FDIM * CDIM);
    mma_gemm<false, 2><<<dim3(CDIM / BN, NPAIR / BM, EDIM), 256, SMEM_BYTES>>>(
        midh, w2h, w2l, out, nullptr, CDIM, FDIM, bin_tok, bin_w, counts, offs, (size_t)CDIM * FDIM);
}

// round 7
// speedup vs baseline: 3.2474x; 1.1671x over previous
#include <cuda_runtime.h>
#include <cuda_fp16.h>
#include <cstdint>
#include <math.h>

// Problem constants
#define NTOK   4096
#define CDIM   1024
#define EDIM   8
#define FDIM   1024
#define FSDIM  2048
#define NPAIR  8192

// ---------------- scratch ----------------
__device__ __half g_xh[NTOK * CDIM];                                  // activations, fp16
__device__ __half g_w1h[EDIM * FDIM * CDIM], g_w1l[EDIM * FDIM * CDIM];
__device__ __half g_w2h[EDIM * CDIM * FDIM];                          // single fp16 (3-pass scheme)
__device__ __half g_ws1h[FSDIM * CDIM], g_ws1l[FSDIM * CDIM];
__device__ __half g_ws2h[CDIM * FSDIM];                               // single fp16
__device__ __half g_midh[NPAIR * FDIM];                               // intermediate, fp16
__device__ int   g_counts[EDIM];
__device__ int   g_fill[EDIM];
__device__ int   g_off[EDIM];
__device__ int   g_tok_e[NPAIR];
__device__ float g_tok_w[NPAIR];
__device__ int   g_bin_tok[NPAIR];
__device__ float g_bin_w[NPAIR];

// ---------------- helpers ----------------
__device__ __forceinline__ uint32_t smem_u32(const void* p) {
    uint32_t a;
    asm("{ .reg .u64 t; cvta.to.shared.u64 t, %1; cvt.u32.u64 %0, t; }" : "=r"(a) : "l"(p));
    return a;
}
__device__ __forceinline__ void cp_async16(uint32_t dst, const void* src) {
    asm volatile("cp.async.ca.shared.global [%0], [%1], 16;" :: "r"(dst), "l"(src));
}
#define CP_COMMIT()  asm volatile("cp.async.commit_group;" ::: "memory")
#define CP_WAIT_2()  asm volatile("cp.async.wait_group 2;" ::: "memory")

__device__ __forceinline__ void mma_f16(float* c, const uint32_t* a, const uint32_t* b) {
    asm volatile(
        "mma.sync.aligned.m16n8k16.row.col.f32.f16.f16.f32 "
        "{%0,%1,%2,%3}, {%4,%5,%6,%7}, {%8,%9}, {%0,%1,%2,%3};"
        : "+f"(c[0]), "+f"(c[1]), "+f"(c[2]), "+f"(c[3])
        : "r"(a[0]), "r"(a[1]), "r"(a[2]), "r"(a[3]), "r"(b[0]), "r"(b[1]));
}
__device__ __forceinline__ float sqrelu(float v) { return v > 0.f ? v * v : 0.f; }

// ---------------- conversions ----------------
__global__ void cvt_half_kernel(const float* __restrict__ src, __half* __restrict__ h, int n) {
    int i = (blockIdx.x * blockDim.x + threadIdx.x) * 4;
    if (i >= n) return;
    float4 v = *(const float4*)(src + i);
    ushort4 hh;
    hh.x = __half_as_ushort(__float2half_rn(v.x));
    hh.y = __half_as_ushort(__float2half_rn(v.y));
    hh.z = __half_as_ushort(__float2half_rn(v.z));
    hh.w = __half_as_ushort(__float2half_rn(v.w));
    *(ushort4*)(h + i) = hh;
}

__global__ void split_half_kernel(const float* __restrict__ src,
                                  __half* __restrict__ h, __half* __restrict__ l, int n) {
    int i = (blockIdx.x * blockDim.x + threadIdx.x) * 4;
    if (i >= n) return;
    float4 v = *(const float4*)(src + i);
    float vv[4] = {v.x, v.y, v.z, v.w};
    ushort4 hh, ll;
    unsigned short* hp = &hh.x; unsigned short* lp = &ll.x;
    #pragma unroll
    for (int k = 0; k < 4; k++) {
        __half bh = __float2half_rn(vv[k]);
        hp[k] = __half_as_ushort(bh);
        lp[k] = __half_as_ushort(__float2half_rn(vv[k] - __half2float(bh)));
    }
    *(ushort4*)(h + i) = hh;
    *(ushort4*)(l + i) = ll;
}

// ---------------- routing ----------------
__global__ void init_kernel() {
    int i = threadIdx.x;
    if (i < EDIM) { g_counts[i] = 0; g_fill[i] = 0; }
}

__global__ void router_kernel(const float* __restrict__ x, const float* __restrict__ wr) {
    int gw = (blockIdx.x * blockDim.x + threadIdx.x) >> 5;
    int lane = threadIdx.x & 31;
    if (gw >= NTOK) return;
    const float* xr = x + (size_t)gw * CDIM;
    float acc[EDIM] = {0.f, 0.f, 0.f, 0.f, 0.f, 0.f, 0.f, 0.f};
    for (int c = lane; c < CDIM; c += 32) {
        float xv = xr[c];
        #pragma unroll
        for (int e = 0; e < EDIM; e++) acc[e] = fmaf(xv, wr[e * CDIM + c], acc[e]);
    }
    #pragma unroll
    for (int e = 0; e < EDIM; e++) {
        #pragma unroll
        for (int o = 16; o; o >>= 1) acc[e] += __shfl_xor_sync(0xffffffffu, acc[e], o);
    }
    if (lane == 0) {
        float m = acc[0];
        #pragma unroll
        for (int e = 1; e < EDIM; e++) m = fmaxf(m, acc[e]);
        float p[EDIM];
        #pragma unroll
        for (int e = 0; e < EDIM; e++) p[e] = expf(acc[e] - m);
        int i0 = 0; float p0 = p[0];
        #pragma unroll
        for (int e = 1; e < EDIM; e++) if (p[e] > p0) { p0 = p[e]; i0 = e; }
        int i1 = -1; float p1 = -1.f;
        #pragma unroll
        for (int e = 0; e < EDIM; e++) if (e != i0 && p[e] > p1) { p1 = p[e]; i1 = e; }
        float s = p0 + p1;
        g_tok_e[2 * gw + 0] = i0;  g_tok_w[2 * gw + 0] = p0 / s;
        g_tok_e[2 * gw + 1] = i1;  g_tok_w[2 * gw + 1] = p1 / s;
        atomicAdd(&g_counts[i0], 1);
        atomicAdd(&g_counts[i1], 1);
    }
}

__global__ void offsets_kernel() {
    if (threadIdx.x == 0) {
        int s = 0;
        for (int e = 0; e < EDIM; e++) { g_off[e] = s; s += g_counts[e]; }
    }
}

__global__ void assign_kernel() {
    int t = blockIdx.x * blockDim.x + threadIdx.x;
    if (t >= NTOK) return;
    #pragma unroll
    for (int k = 0; k < 2; k++) {
        int e = g_tok_e[2 * t + k];
        int slot = atomicAdd(&g_fill[e], 1);
        int r = g_off[e] + slot;
        g_bin_tok[r] = t;
        g_bin_w[r]   = g_tok_w[2 * t + k];
    }
}

// ---------------- mma.sync GEMM, cp.async multistage, single-sync pipeline ----------------
// Out[m,n] = sum_k A[m,k]*B[n,k].  A = fp16.  SPLITB: B = Bh + Bl (two passes); else B = Bh.
// EPI: 0 = sqrelu -> fp16 OutH row (rowbase+m); 1 = fp32 OutF row m; 2 = atomicAdd(OutF[rowmap*N], w*v)
#define BM 128
#define BN 128
#define BKF 32
#define NSTAGE 4
#define B_HI 2048
#define B_LO 4096

template<bool GATHER, int EPI, bool SPLITB>
__global__ __launch_bounds__(256, 2) void mma_gemm(
    const __half* __restrict__ A,
    const __half* __restrict__ Bhb, const __half* __restrict__ Blb,
    float* __restrict__ OutF, __half* __restrict__ OutH,
    int N, int K,
    const int* __restrict__ rowmap, const float* __restrict__ roww,
    const int* __restrict__ counts, const int* __restrict__ offs, size_t bStride)
{
    constexpr int STW = SPLITB ? 6144 : 4096;   // stage words: A(2048) Bh(2048) [Bl(2048)]

    const int e    = blockIdx.z;
    const int Mtot = counts ? counts[e] : (int)(gridDim.y * BM);
    const int m0   = blockIdx.y * BM;
    if (m0 >= Mtot) return;
    const int rowbase = offs ? offs[e] : 0;
    const int n0   = blockIdx.x * BN;
    const __half* Bh = Bhb + (size_t)e * bStride;
    const __half* Bl = SPLITB ? (Blb + (size_t)e * bStride) : nullptr;

    extern __shared__ uint32_t smw[];
    const uint32_t sm0 = smem_u32(smw);

    const int tid  = threadIdx.x;
    const int wid  = tid >> 5, lane = tid & 31;
    const int wm   = wid >> 2, wn = wid & 3;

    // loader: thread owns 2 chunks (row, k-octet) of each operand
    const __half *pa[2], *pbh[2], *pbl[2];
    uint32_t aoff[2], boff[2];
    #pragma unroll
    for (int j = 0; j < 2; j++) {
        int c = tid + j * 256;
        int row = c >> 2, o = c & 3;
        int am = m0 + row;
        size_t arow;
        if (GATHER) arow = (size_t)rowmap[rowbase + (am < Mtot ? am : 0)];
        else        arow = (size_t)(rowbase + (am < Mtot ? am : m0));
        pa[j]  = A  + arow * K + o * 8;
        pbh[j] = Bh + (size_t)(n0 + row) * K + o * 8;
        if (SPLITB) pbl[j] = Bl + (size_t)(n0 + row) * K + o * 8;
        int ks = o >> 1, ch = o & 1;
        aoff[j] = (uint32_t)(((ks * 8 + (row >> 4)) * 4 + (((row >> 3) & 1) + 2 * ch)) * 32 + (row & 7) * 4) * 4u;
        boff[j] = (uint32_t)(((ks * 16 + (row >> 3)) * 2 + ch) * 32 + (row & 7) * 4) * 4u;
    }

    const int nK = K / BKF;

    float acc[4][4][4];
    #pragma unroll
    for (int i = 0; i < 4; i++)
        #pragma unroll
        for (int j = 0; j < 4; j++)
            #pragma unroll
            for (int r = 0; r < 4; r++) acc[i][j][r] = 0.f;

    auto issue = [&](int kt) {
        if (kt < nK) {
            const uint32_t sb = sm0 + (kt % NSTAGE) * (STW * 4);
            const int kadv = kt * BKF;
            #pragma unroll
            for (int j = 0; j < 2; j++) {
                cp_async16(sb +            aoff[j], pa[j]  + kadv);
                cp_async16(sb + B_HI * 4 + boff[j], pbh[j] + kadv);
                if (SPLITB) cp_async16(sb + B_LO * 4 + boff[j], pbl[j] + kadv);
            }
        }
        CP_COMMIT();
    };

    issue(0); issue(1); issue(2);

    for (int kt = 0; kt < nK; kt++) {
        CP_WAIT_2();             // stage kt resident
        __syncthreads();         // all warps: stage kt visible AND compute(kt-1) done
        issue(kt + 3);           // refill buffer (kt+3)%4 == (kt-1)%4 — safe after sync
        const uint32_t sb = (kt % NSTAGE) * STW;

        #pragma unroll
        for (int s = 0; s < 2; s++) {
            uint32_t bh[4][2], bl[4][2];
            #pragma unroll
            for (int j = 0; j < 4; j++) {
                uint32_t off = (uint32_t)(((s * 16 + wn * 4 + j) * 2) * 32 + lane);
                bh[j][0] = smw[sb + B_HI + off];  bh[j][1] = smw[sb + B_HI + off + 32];
                if (SPLITB) {
                    bl[j][0] = smw[sb + B_LO + off];  bl[j][1] = smw[sb + B_LO + off + 32];
                }
            }
            #pragma unroll
            for (int i = 0; i < 4; i++) {
                uint32_t a[4];
                uint32_t off = (uint32_t)(((s * 8 + wm * 4 + i) * 4) * 32 + lane);
                #pragma unroll
                for (int r = 0; r < 4; r++) a[r] = smw[sb + off + r * 32];
                #pragma unroll
                for (int j = 0; j < 4; j++) mma_f16(acc[i][j], a, bh[j]);
                if (SPLITB) {
                    #pragma unroll
                    for (int j = 0; j < 4; j++) mma_f16(acc[i][j], a, bl[j]);
                }
            }
        }
    }

    // ---- epilogue ----
    #pragma unroll
    for (int i = 0; i < 4; i++) {
        const int rbase = m0 + wm * 64 + i * 16 + (lane >> 2);
        #pragma unroll
        for (int half = 0; half < 2; half++) {
            const int mrow = rbase + half * 8;
            if (mrow >= Mtot) continue;
            int tok = 0; float w = 0.f;
            if (EPI == 2) { tok = rowmap[rowbase + mrow]; w = roww[rowbase + mrow]; }
            #pragma unroll
            for (int j = 0; j < 4; j++) {
                const int col = n0 + wn * 32 + j * 8 + (lane & 3) * 2;
                float v0 = acc[i][j][half * 2 + 0];
                float v1 = acc[i][j][half * 2 + 1];
                if (EPI == 0) {
                    __half2 h2 = __floats2half2_rn(sqrelu(v0), sqrelu(v1));
                    *(__half2*)(OutH + (size_t)(rowbase + mrow) * N + col) = h2;
                } else if (EPI == 1) {
                    float2 o2; o2.x = v0; o2.y = v1;
                    *(float2*)&OutF[(size_t)mrow * N + col] = o2;
                } else {
                    atomicAdd(&OutF[(size_t)tok * N + col],     w * v0);
                    atomicAdd(&OutF[(size_t)tok * N + col + 1], w * v1);
                }
            }
        }
    }
}

// ---------------- launch ----------------
#define SMEM_SPLIT (NSTAGE * 6144 * 4)   // 96 KB
#define SMEM_SINGLE (NSTAGE * 4096 * 4)  // 64 KB

extern "C" void kernel_launch(void* const* d_in, const int* in_sizes, int n_in,
                              void* d_out, int out_size) {
    const float* x   = (const float*)d_in[0];
    const float* wr  = (const float*)d_in[1];
    const float* w1  = (const float*)d_in[2];   // (E, F, C)
    const float* w2  = (const float*)d_in[3];   // (E, C, F)
    const float* ws1 = (const float*)d_in[4];   // (FS, C)
    const float* ws2 = (const float*)d_in[5];   // (C, FS)
    float* out = (float*)d_out;

    __half *xh, *w1h, *w1l, *w2h, *ws1h, *ws1l, *ws2h, *midh;
    cudaGetSymbolAddress((void**)&xh,   g_xh);
    cudaGetSymbolAddress((void**)&w1h,  g_w1h);  cudaGetSymbolAddress((void**)&w1l,  g_w1l);
    cudaGetSymbolAddress((void**)&w2h,  g_w2h);
    cudaGetSymbolAddress((void**)&ws1h, g_ws1h); cudaGetSymbolAddress((void**)&ws1l, g_ws1l);
    cudaGetSymbolAddress((void**)&ws2h, g_ws2h);
    cudaGetSymbolAddress((void**)&midh, g_midh);
    int *bin_tok, *counts, *offs; float* bin_w;
    cudaGetSymbolAddress((void**)&bin_tok, g_bin_tok);
    cudaGetSymbolAddress((void**)&bin_w,   g_bin_w);
    cudaGetSymbolAddress((void**)&counts,  g_counts);
    cudaGetSymbolAddress((void**)&offs,    g_off);

    cudaFuncSetAttribute(mma_gemm<false, 0, true >, cudaFuncAttributeMaxDynamicSharedMemorySize, SMEM_SPLIT);
    cudaFuncSetAttribute(mma_gemm<true,  0, true >, cudaFuncAttributeMaxDynamicSharedMemorySize, SMEM_SPLIT);
    cudaFuncSetAttribute(mma_gemm<false, 1, false>, cudaFuncAttributeMaxDynamicSharedMemorySize, SMEM_SINGLE);
    cudaFuncSetAttribute(mma_gemm<false, 2, false>, cudaFuncAttributeMaxDynamicSharedMemorySize, SMEM_SINGLE);

    // conversions
    cvt_half_kernel<<<(NTOK * CDIM / 4 + 255) / 256, 256>>>(x, xh, NTOK * CDIM);
    split_half_kernel<<<(FSDIM * CDIM / 4 + 255) / 256, 256>>>(ws1, ws1h, ws1l, FSDIM * CDIM);
    cvt_half_kernel<<<(CDIM * FSDIM / 4 + 255) / 256, 256>>>(ws2, ws2h, CDIM * FSDIM);
    split_half_kernel<<<(EDIM * FDIM * CDIM / 4 + 255) / 256, 256>>>(w1, w1h, w1l, EDIM * FDIM * CDIM);
    cvt_half_kernel<<<(EDIM * CDIM * FDIM / 4 + 255) / 256, 256>>>(w2, w2h, EDIM * CDIM * FDIM);

    // routing
    init_kernel<<<1, 32>>>();
    router_kernel<<<(NTOK * 32) / 256, 256>>>(x, wr);
    offsets_kernel<<<1, 32>>>();
    assign_kernel<<<(NTOK + 255) / 256, 256>>>();

    // shared expert: mid = sqrelu(x @ ws1^T); out = mid @ ws2^T
    mma_gemm<false, 0, true><<<dim3(FSDIM / BN, NTOK / BM, 1), 256, SMEM_SPLIT>>>(
        xh, ws1h, ws1l, nullptr, midh, FSDIM, CDIM, nullptr, nullptr, nullptr, nullptr, 0);
    mma_gemm<false, 1, false><<<dim3(CDIM / BN, NTOK / BM, 1), 256, SMEM_SINGLE>>>(
        midh, ws2h, nullptr, out, nullptr, CDIM, FSDIM, nullptr, nullptr, nullptr, nullptr, 0);

    // MoE experts: gather -> FFN1 -> sqrelu -> FFN2 -> weighted scatter-add
    mma_gemm<true, 0, true><<<dim3(FDIM / BN, NPAIR / BM, EDIM), 256, SMEM_SPLIT>>>(
        xh, w1h, w1l, nullptr, midh, FDIM, CDIM, bin_tok, nullptr, counts, offs, (size_t)FDIM * CDIM);
    mma_gemm<false, 2, false><<<dim3(CDIM / BN, NPAIR / BM, EDIM), 256, SMEM_SINGLE>>>(
        midh, w2h, nullptr, out, nullptr, CDIM, FDIM, bin_tok, bin_w, counts, offs, (size_t)CDIM * FDIM);
}

// round 8
// speedup vs baseline: 4.1789x; 1.2868x over previous
#include <cuda_runtime.h>
#include <cuda_fp16.h>
#include <cstdint>
#include <math.h>

// Problem constants
#define NTOK   4096
#define CDIM   1024
#define EDIM   8
#define FDIM   1024
#define FSDIM  2048
#define NPAIR  8192

// ---------------- scratch (all operands single fp16) ----------------
__device__ __half g_xh[NTOK * CDIM];
__device__ __half g_w1h[EDIM * FDIM * CDIM];
__device__ __half g_w2h[EDIM * CDIM * FDIM];
__device__ __half g_ws1h[FSDIM * CDIM];
__device__ __half g_ws2h[CDIM * FSDIM];
__device__ __half g_midmoe[NPAIR * FDIM];    // MoE intermediate (8192 x 1024)
__device__ __half g_midsh[NTOK * FSDIM];     // shared-expert intermediate (4096 x 2048)
__device__ int   g_counts[EDIM];
__device__ int   g_fill[EDIM];
__device__ int   g_off[EDIM];
__device__ int   g_tok_e[NPAIR];
__device__ float g_tok_w[NPAIR];
__device__ int   g_bin_tok[NPAIR];
__device__ float g_bin_w[NPAIR];

// ---------------- helpers ----------------
__device__ __forceinline__ uint32_t smem_u32(const void* p) {
    uint32_t a;
    asm("{ .reg .u64 t; cvta.to.shared.u64 t, %1; cvt.u32.u64 %0, t; }" : "=r"(a) : "l"(p));
    return a;
}
__device__ __forceinline__ void cp_async16(uint32_t dst, const void* src) {
    asm volatile("cp.async.ca.shared.global [%0], [%1], 16;" :: "r"(dst), "l"(src));
}
#define CP_COMMIT()  asm volatile("cp.async.commit_group;" ::: "memory")
#define CP_WAIT_2()  asm volatile("cp.async.wait_group 2;" ::: "memory")

__device__ __forceinline__ void mma_f16(float* c, const uint32_t* a, const uint32_t* b) {
    asm volatile(
        "mma.sync.aligned.m16n8k16.row.col.f32.f16.f16.f32 "
        "{%0,%1,%2,%3}, {%4,%5,%6,%7}, {%8,%9}, {%0,%1,%2,%3};"
        : "+f"(c[0]), "+f"(c[1]), "+f"(c[2]), "+f"(c[3])
        : "r"(a[0]), "r"(a[1]), "r"(a[2]), "r"(a[3]), "r"(b[0]), "r"(b[1]));
}
__device__ __forceinline__ float sqrelu(float v) { return v > 0.f ? v * v : 0.f; }

// ---------------- conversion ----------------
__global__ void cvt_half_kernel(const float* __restrict__ src, __half* __restrict__ h, int n) {
    int i = (blockIdx.x * blockDim.x + threadIdx.x) * 4;
    if (i >= n) return;
    float4 v = *(const float4*)(src + i);
    ushort4 hh;
    hh.x = __half_as_ushort(__float2half_rn(v.x));
    hh.y = __half_as_ushort(__float2half_rn(v.y));
    hh.z = __half_as_ushort(__float2half_rn(v.z));
    hh.w = __half_as_ushort(__float2half_rn(v.w));
    *(ushort4*)(h + i) = hh;
}

// ---------------- routing ----------------
__global__ void init_kernel() {
    int i = threadIdx.x;
    if (i < EDIM) { g_counts[i] = 0; g_fill[i] = 0; }
}

__global__ void router_kernel(const float* __restrict__ x, const float* __restrict__ wr) {
    int gw = (blockIdx.x * blockDim.x + threadIdx.x) >> 5;
    int lane = threadIdx.x & 31;
    if (gw >= NTOK) return;
    const float* xr = x + (size_t)gw * CDIM;
    float acc[EDIM] = {0.f, 0.f, 0.f, 0.f, 0.f, 0.f, 0.f, 0.f};
    for (int c = lane; c < CDIM; c += 32) {
        float xv = xr[c];
        #pragma unroll
        for (int e = 0; e < EDIM; e++) acc[e] = fmaf(xv, wr[e * CDIM + c], acc[e]);
    }
    #pragma unroll
    for (int e = 0; e < EDIM; e++) {
        #pragma unroll
        for (int o = 16; o; o >>= 1) acc[e] += __shfl_xor_sync(0xffffffffu, acc[e], o);
    }
    if (lane == 0) {
        float m = acc[0];
        #pragma unroll
        for (int e = 1; e < EDIM; e++) m = fmaxf(m, acc[e]);
        float p[EDIM];
        #pragma unroll
        for (int e = 0; e < EDIM; e++) p[e] = expf(acc[e] - m);
        int i0 = 0; float p0 = p[0];
        #pragma unroll
        for (int e = 1; e < EDIM; e++) if (p[e] > p0) { p0 = p[e]; i0 = e; }
        int i1 = -1; float p1 = -1.f;
        #pragma unroll
        for (int e = 0; e < EDIM; e++) if (e != i0 && p[e] > p1) { p1 = p[e]; i1 = e; }
        float s = p0 + p1;
        g_tok_e[2 * gw + 0] = i0;  g_tok_w[2 * gw + 0] = p0 / s;
        g_tok_e[2 * gw + 1] = i1;  g_tok_w[2 * gw + 1] = p1 / s;
        atomicAdd(&g_counts[i0], 1);
        atomicAdd(&g_counts[i1], 1);
    }
}

__global__ void offsets_kernel() {
    if (threadIdx.x == 0) {
        int s = 0;
        for (int e = 0; e < EDIM; e++) { g_off[e] = s; s += g_counts[e]; }
    }
}

__global__ void assign_kernel() {
    int t = blockIdx.x * blockDim.x + threadIdx.x;
    if (t >= NTOK) return;
    #pragma unroll
    for (int k = 0; k < 2; k++) {
        int e = g_tok_e[2 * t + k];
        int slot = atomicAdd(&g_fill[e], 1);
        int r = g_off[e] + slot;
        g_bin_tok[r] = t;
        g_bin_w[r]   = g_tok_w[2 * t + k];
    }
}

// ---------------- GEMM core constants ----------------
#define BM 128
#define BN 128
#define BKF 32
#define NSTAGE 4
#define STW 4096                       // stage words: A(2048) B(2048)
#define B_HI 2048
#define SMEM_BYTES (NSTAGE * STW * 4)  // 64 KB

// ============ fused GEMM1: z<EDIM -> expert e (gather), z==EDIM -> shared expert ============
// Out = sqrelu(A_rows @ B^T) stored as fp16.
__global__ __launch_bounds__(256, 2) void gemm1_fused(
    const __half* __restrict__ Xh,
    const __half* __restrict__ W1h, const __half* __restrict__ Ws1h,
    __half* __restrict__ MidMoe, __half* __restrict__ MidSh)
{
    const int z = blockIdx.z;
    const bool moe = (z < EDIM);
    const int Mtot = moe ? g_counts[z] : NTOK;
    const int m0   = blockIdx.y * BM;
    if (m0 >= Mtot) return;
    const int N    = moe ? FDIM : FSDIM;
    const int n0   = blockIdx.x * BN;
    if (n0 >= N) return;
    const int rowbase = moe ? g_off[z] : 0;
    const int K = CDIM;
    const __half* B = moe ? (W1h + (size_t)z * FDIM * CDIM) : Ws1h;
    __half* Out = moe ? MidMoe : MidSh;

    extern __shared__ uint32_t smw[];
    const uint32_t sm0 = smem_u32(smw);

    const int tid  = threadIdx.x;
    const int wid  = tid >> 5, lane = tid & 31;
    const int wm   = wid >> 2, wn = wid & 3;

    const __half *pa[2], *pb[2];
    uint32_t aoff[2], boff[2];
    #pragma unroll
    for (int j = 0; j < 2; j++) {
        int c = tid + j * 256;
        int row = c >> 2, o = c & 3;
        int am = m0 + row;
        size_t arow;
        if (moe) arow = (size_t)g_bin_tok[rowbase + (am < Mtot ? am : 0)];
        else     arow = (size_t)(am < Mtot ? am : m0);
        pa[j] = Xh + arow * K + o * 8;
        pb[j] = B + (size_t)(n0 + row) * K + o * 8;
        int ks = o >> 1, ch = o & 1;
        aoff[j] = (uint32_t)(((ks * 8 + (row >> 4)) * 4 + (((row >> 3) & 1) + 2 * ch)) * 32 + (row & 7) * 4) * 4u;
        boff[j] = (uint32_t)(((ks * 16 + (row >> 3)) * 2 + ch) * 32 + (row & 7) * 4) * 4u;
    }

    const int nK = K / BKF;
    float acc[4][4][4];
    #pragma unroll
    for (int i = 0; i < 4; i++)
        #pragma unroll
        for (int j = 0; j < 4; j++)
            #pragma unroll
            for (int r = 0; r < 4; r++) acc[i][j][r] = 0.f;

    auto issue = [&](int kt) {
        if (kt < nK) {
            const uint32_t sb = sm0 + (kt % NSTAGE) * (STW * 4);
            const int kadv = kt * BKF;
            #pragma unroll
            for (int j = 0; j < 2; j++) {
                cp_async16(sb +            aoff[j], pa[j] + kadv);
                cp_async16(sb + B_HI * 4 + boff[j], pb[j] + kadv);
            }
        }
        CP_COMMIT();
    };

    issue(0); issue(1); issue(2);

    for (int kt = 0; kt < nK; kt++) {
        CP_WAIT_2();
        __syncthreads();
        issue(kt + 3);
        const uint32_t sb = (kt % NSTAGE) * STW;
        #pragma unroll
        for (int s = 0; s < 2; s++) {
            uint32_t bf[4][2];
            #pragma unroll
            for (int j = 0; j < 4; j++) {
                uint32_t off = (uint32_t)(((s * 16 + wn * 4 + j) * 2) * 32 + lane);
                bf[j][0] = smw[sb + B_HI + off];  bf[j][1] = smw[sb + B_HI + off + 32];
            }
            #pragma unroll
            for (int i = 0; i < 4; i++) {
                uint32_t a[4];
                uint32_t off = (uint32_t)(((s * 8 + wm * 4 + i) * 4) * 32 + lane);
                #pragma unroll
                for (int r = 0; r < 4; r++) a[r] = smw[sb + off + r * 32];
                #pragma unroll
                for (int j = 0; j < 4; j++) mma_f16(acc[i][j], a, bf[j]);
            }
        }
    }

    #pragma unroll
    for (int i = 0; i < 4; i++) {
        const int rbase = m0 + wm * 64 + i * 16 + (lane >> 2);
        #pragma unroll
        for (int half = 0; half < 2; half++) {
            const int mrow = rbase + half * 8;
            if (mrow >= Mtot) continue;
            #pragma unroll
            for (int j = 0; j < 4; j++) {
                const int col = n0 + wn * 32 + j * 8 + (lane & 3) * 2;
                __half2 h2 = __floats2half2_rn(sqrelu(acc[i][j][half * 2 + 0]),
                                               sqrelu(acc[i][j][half * 2 + 1]));
                *(__half2*)(Out + (size_t)(rowbase + mrow) * N + col) = h2;
            }
        }
    }
}

// ============ GEMM2: EPI 1 = plain fp32 store; EPI 2 = weighted atomic scatter ============
template<int EPI>
__global__ __launch_bounds__(256, 2) void mma_gemm2(
    const __half* __restrict__ A,
    const __half* __restrict__ Bhb,
    float* __restrict__ OutF,
    int N, int K,
    const int* __restrict__ rowmap, const float* __restrict__ roww,
    const int* __restrict__ counts, const int* __restrict__ offs, size_t bStride)
{
    const int e    = blockIdx.z;
    const int Mtot = counts ? counts[e] : (int)(gridDim.y * BM);
    const int m0   = blockIdx.y * BM;
    if (m0 >= Mtot) return;
    const int rowbase = offs ? offs[e] : 0;
    const int n0   = blockIdx.x * BN;
    const __half* B = Bhb + (size_t)e * bStride;

    extern __shared__ uint32_t smw[];
    const uint32_t sm0 = smem_u32(smw);

    const int tid  = threadIdx.x;
    const int wid  = tid >> 5, lane = tid & 31;
    const int wm   = wid >> 2, wn = wid & 3;

    const __half *pa[2], *pb[2];
    uint32_t aoff[2], boff[2];
    #pragma unroll
    for (int j = 0; j < 2; j++) {
        int c = tid + j * 256;
        int row = c >> 2, o = c & 3;
        int am = m0 + row;
        size_t arow = (size_t)(rowbase + (am < Mtot ? am : m0));
        pa[j] = A + arow * K + o * 8;
        pb[j] = B + (size_t)(n0 + row) * K + o * 8;
        int ks = o >> 1, ch = o & 1;
        aoff[j] = (uint32_t)(((ks * 8 + (row >> 4)) * 4 + (((row >> 3) & 1) + 2 * ch)) * 32 + (row & 7) * 4) * 4u;
        boff[j] = (uint32_t)(((ks * 16 + (row >> 3)) * 2 + ch) * 32 + (row & 7) * 4) * 4u;
    }

    const int nK = K / BKF;
    float acc[4][4][4];
    #pragma unroll
    for (int i = 0; i < 4; i++)
        #pragma unroll
        for (int j = 0; j < 4; j++)
            #pragma unroll
            for (int r = 0; r < 4; r++) acc[i][j][r] = 0.f;

    auto issue = [&](int kt) {
        if (kt < nK) {
            const uint32_t sb = sm0 + (kt % NSTAGE) * (STW * 4);
            const int kadv = kt * BKF;
            #pragma unroll
            for (int j = 0; j < 2; j++) {
                cp_async16(sb +            aoff[j], pa[j] + kadv);
                cp_async16(sb + B_HI * 4 + boff[j], pb[j] + kadv);
            }
        }
        CP_COMMIT();
    };

    issue(0); issue(1); issue(2);

    for (int kt = 0; kt < nK; kt++) {
        CP_WAIT_2();
        __syncthreads();
        issue(kt + 3);
        const uint32_t sb = (kt % NSTAGE) * STW;
        #pragma unroll
        for (int s = 0; s < 2; s++) {
            uint32_t bf[4][2];
            #pragma unroll
            for (int j = 0; j < 4; j++) {
                uint32_t off = (uint32_t)(((s * 16 + wn * 4 + j) * 2) * 32 + lane);
                bf[j][0] = smw[sb + B_HI + off];  bf[j][1] = smw[sb + B_HI + off + 32];
            }
            #pragma unroll
            for (int i = 0; i < 4; i++) {
                uint32_t a[4];
                uint32_t off = (uint32_t)(((s * 8 + wm * 4 + i) * 4) * 32 + lane);
                #pragma unroll
                for (int r = 0; r < 4; r++) a[r] = smw[sb + off + r * 32];
                #pragma unroll
                for (int j = 0; j < 4; j++) mma_f16(acc[i][j], a, bf[j]);
            }
        }
    }

    #pragma unroll
    for (int i = 0; i < 4; i++) {
        const int rbase = m0 + wm * 64 + i * 16 + (lane >> 2);
        #pragma unroll
        for (int half = 0; half < 2; half++) {
            const int mrow = rbase + half * 8;
            if (mrow >= Mtot) continue;
            int tok = 0; float w = 0.f;
            if (EPI == 2) { tok = rowmap[rowbase + mrow]; w = roww[rowbase + mrow]; }
            #pragma unroll
            for (int j = 0; j < 4; j++) {
                const int col = n0 + wn * 32 + j * 8 + (lane & 3) * 2;
                float v0 = acc[i][j][half * 2 + 0];
                float v1 = acc[i][j][half * 2 + 1];
                if (EPI == 1) {
                    float2 o2; o2.x = v0; o2.y = v1;
                    *(float2*)&OutF[(size_t)mrow * N + col] = o2;
                } else {
                    atomicAdd(&OutF[(size_t)tok * N + col],     w * v0);
                    atomicAdd(&OutF[(size_t)tok * N + col + 1], w * v1);
                }
            }
        }
    }
}

// ---------------- launch ----------------
extern "C" void kernel_launch(void* const* d_in, const int* in_sizes, int n_in,
                              void* d_out, int out_size) {
    const float* x   = (const float*)d_in[0];
    const float* wr  = (const float*)d_in[1];
    const float* w1  = (const float*)d_in[2];   // (E, F, C)
    const float* w2  = (const float*)d_in[3];   // (E, C, F)
    const float* ws1 = (const float*)d_in[4];   // (FS, C)
    const float* ws2 = (const float*)d_in[5];   // (C, FS)
    float* out = (float*)d_out;

    __half *xh, *w1h, *w2h, *ws1h, *ws2h, *midmoe, *midsh;
    cudaGetSymbolAddress((void**)&xh,     g_xh);
    cudaGetSymbolAddress((void**)&w1h,    g_w1h);
    cudaGetSymbolAddress((void**)&w2h,    g_w2h);
    cudaGetSymbolAddress((void**)&ws1h,   g_ws1h);
    cudaGetSymbolAddress((void**)&ws2h,   g_ws2h);
    cudaGetSymbolAddress((void**)&midmoe, g_midmoe);
    cudaGetSymbolAddress((void**)&midsh,  g_midsh);
    int *bin_tok, *counts, *offs; float* bin_w;
    cudaGetSymbolAddress((void**)&bin_tok, g_bin_tok);
    cudaGetSymbolAddress((void**)&bin_w,   g_bin_w);
    cudaGetSymbolAddress((void**)&counts,  g_counts);
    cudaGetSymbolAddress((void**)&offs,    g_off);

    cudaFuncSetAttribute(gemm1_fused,   cudaFuncAttributeMaxDynamicSharedMemorySize, SMEM_BYTES);
    cudaFuncSetAttribute(mma_gemm2<1>,  cudaFuncAttributeMaxDynamicSharedMemorySize, SMEM_BYTES);
    cudaFuncSetAttribute(mma_gemm2<2>,  cudaFuncAttributeMaxDynamicSharedMemorySize, SMEM_BYTES);

    // conversions (all single fp16)
    cvt_half_kernel<<<(NTOK * CDIM / 4 + 255) / 256, 256>>>(x, xh, NTOK * CDIM);
    cvt_half_kernel<<<(FSDIM * CDIM / 4 + 255) / 256, 256>>>(ws1, ws1h, FSDIM * CDIM);
    cvt_half_kernel<<<(CDIM * FSDIM / 4 + 255) / 256, 256>>>(ws2, ws2h, CDIM * FSDIM);
    cvt_half_kernel<<<(EDIM * FDIM * CDIM / 4 + 255) / 256, 256>>>(w1, w1h, EDIM * FDIM * CDIM);
    cvt_half_kernel<<<(EDIM * CDIM * FDIM / 4 + 255) / 256, 256>>>(w2, w2h, EDIM * CDIM * FDIM);

    // routing
    init_kernel<<<1, 32>>>();
    router_kernel<<<(NTOK * 32) / 256, 256>>>(x, wr);
    offsets_kernel<<<1, 32>>>();
    assign_kernel<<<(NTOK + 255) / 256, 256>>>();

    // fused GEMM1: experts (z=0..7, gather from xh) + shared expert (z=8)
    // grid.x covers max(FDIM,FSDIM)/BN = 16; grid.y covers NPAIR/BM = 64
    gemm1_fused<<<dim3(FSDIM / BN, NPAIR / BM, EDIM + 1), 256, SMEM_BYTES>>>(
        xh, w1h, ws1h, midmoe, midsh);

    // GEMM2: shared expert writes out (plain), then MoE scatter-adds on top
    mma_gemm2<1><<<dim3(CDIM / BN, NTOK / BM, 1), 256, SMEM_BYTES>>>(
        midsh, ws2h, out, CDIM, FSDIM, nullptr, nullptr, nullptr, nullptr, 0);
    mma_gemm2<2><<<dim3(CDIM / BN, NPAIR / BM, EDIM), 256, SMEM_BYTES>>>(
        midmoe, w2h, out, CDIM, FDIM, bin_tok, bin_w, counts, offs, (size_t)CDIM * FDIM);
}